// round 2
// baseline (speedup 1.0000x reference)
#include <cuda_runtime.h>
#include <cuda_bf16.h>
#include <math.h>

// ---------------- problem constants ----------------
#define BATCH 2
#define GRID_DIM 32         // H = W = D = 32
#define C_DIM 192
#define HEADS 6
#define HD 32               // head dim
#define NTOK 64             // tokens per 4x4x4 window
#define NWIN 1024           // B * (32/4)^3
#define M_TOT (NWIN * NTOK) // 65536 rows
#define HID 768
#define SHIFT_AMT 2

// ---------------- scratch (device globals; no allocs) ----------------
__device__ float g_xw[M_TOT * C_DIM];        // LN1 + shifted + window-partitioned
__device__ float g_qkv[3 * NWIN * HEADS * NTOK * HD];
__device__ float g_attnout[M_TOT * C_DIM];   // window layout [wi][n][c]
__device__ float g_xo[M_TOT * C_DIM];        // original layout, residual added
__device__ float g_xn2[M_TOT * C_DIM];       // LN2(xo)
__device__ float g_h1[M_TOT * HID];          // gelu(fc1)

// ---------------- helpers ----------------
__device__ __forceinline__ float gelu_exact(float v) {
    return 0.5f * v * (1.0f + erff(v * 0.70710678118654752f));
}

// Map window-layout row t -> original-layout flat token index (same map is used
// for the forward shift gather and the reverse shift scatter: shifted coord hs
// corresponds to original coord (hs+2) mod 32).
__device__ __forceinline__ int winrow_to_orig(int t) {
    int wi = t >> 6, n = t & 63;
    int b  = wi >> 9;
    int Hb = (wi >> 6) & 7, Wb = (wi >> 3) & 7, Db = wi & 7;
    int i = n >> 4, j = (n >> 2) & 3, k = n & 3;
    int h = ((Hb << 2) + i + SHIFT_AMT) & 31;
    int w = ((Wb << 2) + j + SHIFT_AMT) & 31;
    int d = ((Db << 2) + k + SHIFT_AMT) & 31;
    return (((b * 32 + h) * 32 + w) * 32 + d);
}

// ---------------- LN kernels (warp per token) ----------------
// mode 0: read x at shifted/permuted source, write g_xw (window layout)
// mode 1: read g_xo (original layout), write g_xn2 (original layout)
__global__ __launch_bounds__(256) void ln_kernel(const float* __restrict__ xin,
                                                 const float* __restrict__ gma,
                                                 const float* __restrict__ bta,
                                                 int mode) {
    int warp = threadIdx.x >> 5, lane = threadIdx.x & 31;
    int t = blockIdx.x * 8 + warp;            // token row id (output layout)
    const float* src;
    float* dst;
    if (mode == 0) {
        src = xin + (size_t)winrow_to_orig(t) * C_DIM;
        dst = g_xw + (size_t)t * C_DIM;
    } else {
        src = g_xo + (size_t)t * C_DIM;
        dst = g_xn2 + (size_t)t * C_DIM;
    }
    float v[6];
    float s = 0.f;
#pragma unroll
    for (int k = 0; k < 6; k++) { v[k] = src[lane + 32 * k]; s += v[k]; }
#pragma unroll
    for (int o = 16; o > 0; o >>= 1) s += __shfl_xor_sync(0xffffffffu, s, o);
    float mean = s * (1.0f / C_DIM);
    float q = 0.f;
#pragma unroll
    for (int k = 0; k < 6; k++) { float d = v[k] - mean; q += d * d; }
#pragma unroll
    for (int o = 16; o > 0; o >>= 1) q += __shfl_xor_sync(0xffffffffu, q, o);
    float rstd = rsqrtf(q * (1.0f / C_DIM) + 1e-5f);
#pragma unroll
    for (int k = 0; k < 6; k++) {
        int c = lane + 32 * k;
        dst[c] = (v[k] - mean) * rstd * gma[c] + bta[c];
    }
}

// ---------------- generic tiled SGEMM, 64x64x16, 256 threads, 4x4/thread ---
// mode 0: A=g_xw   [M,192] @ wqkv[192,576] + bqkv -> scatter into g_qkv
// mode 1: A=g_attnout[M,192] @ wo[192,192] + bo, +residual x (permuted) -> g_xo
// mode 2: A=g_xn2  [M,192] @ w1[192,768] + bm1, gelu -> g_h1
// mode 3: A=g_h1   [M,768] @ w2[768,192] + bm2, + g_xo -> dout
__global__ __launch_bounds__(256) void gemm_kernel(const float* __restrict__ Bw,
                                                   const float* __restrict__ bias,
                                                   const float* __restrict__ xres,
                                                   float* __restrict__ dout,
                                                   int K, int N, int mode) {
    const float* A = (mode == 0) ? g_xw
                   : (mode == 1) ? g_attnout
                   : (mode == 2) ? g_xn2
                                 : g_h1;
    __shared__ float As[16][64];
    __shared__ float Bs[16][64];
    int tid = threadIdx.x;
    int tx = tid & 15, ty = tid >> 4;
    int row0 = blockIdx.y * 64, col0 = blockIdx.x * 64;

    int arow = tid >> 2, acol = (tid & 3) * 4;
    int brow = tid >> 4, bcol = (tid & 15) * 4;

    float acc[4][4];
#pragma unroll
    for (int i = 0; i < 4; i++)
#pragma unroll
        for (int j = 0; j < 4; j++) acc[i][j] = 0.f;

    for (int k0 = 0; k0 < K; k0 += 16) {
        float4 av = *(const float4*)&A[(size_t)(row0 + arow) * K + k0 + acol];
        As[acol + 0][arow] = av.x;
        As[acol + 1][arow] = av.y;
        As[acol + 2][arow] = av.z;
        As[acol + 3][arow] = av.w;
        float4 bv = *(const float4*)&Bw[(size_t)(k0 + brow) * N + col0 + bcol];
        *(float4*)&Bs[brow][bcol] = bv;
        __syncthreads();
#pragma unroll
        for (int k = 0; k < 16; k++) {
            float4 a4 = *(float4*)&As[k][ty * 4];
            float4 b4 = *(float4*)&Bs[k][tx * 4];
            float a[4] = {a4.x, a4.y, a4.z, a4.w};
            float b[4] = {b4.x, b4.y, b4.z, b4.w};
#pragma unroll
            for (int i = 0; i < 4; i++)
#pragma unroll
                for (int j = 0; j < 4; j++) acc[i][j] += a[i] * b[j];
        }
        __syncthreads();
    }

#pragma unroll
    for (int ii = 0; ii < 4; ii++) {
        int row = row0 + ty * 4 + ii;
        if (mode == 0) {
            int wi = row >> 6, n = row & 63;
#pragma unroll
            for (int jj = 0; jj < 4; jj++) {
                int col = col0 + tx * 4 + jj;
                float v = acc[ii][jj] + bias[col];
                int which = col / 192;
                int rem = col - which * 192;
                int head = rem >> 5, hdi = rem & 31;
                g_qkv[((((which * NWIN + wi) * HEADS + head) << 11)) + (n << 5) + hdi] = v;
            }
        } else if (mode == 1) {
            int base = winrow_to_orig(row) * C_DIM;
#pragma unroll
            for (int jj = 0; jj < 4; jj++) {
                int col = col0 + tx * 4 + jj;
                float v = acc[ii][jj] + bias[col] + xres[base + col];
                g_xo[base + col] = v;
            }
        } else if (mode == 2) {
#pragma unroll
            for (int jj = 0; jj < 4; jj++) {
                int col = col0 + tx * 4 + jj;
                g_h1[(size_t)row * HID + col] = gelu_exact(acc[ii][jj] + bias[col]);
            }
        } else {
#pragma unroll
            for (int jj = 0; jj < 4; jj++) {
                int col = col0 + tx * 4 + jj;
                size_t o = (size_t)row * C_DIM + col;
                dout[o] = acc[ii][jj] + bias[col] + g_xo[o];
            }
        }
    }
}

// ---------------- attention: one block per (window, head) ----------------
__global__ __launch_bounds__(256) void attn_kernel(const float* __restrict__ bias_table) {
    __shared__ float sQ[NTOK * HD];
    __shared__ float sKT[32][68];
    __shared__ float sV[NTOK * HD];
    __shared__ float sS[64][65];
    __shared__ float sBias[343];
    __shared__ unsigned char sReg[64];

    int wi = blockIdx.x / HEADS, head = blockIdx.x % HEADS;
    int tid = threadIdx.x;

    int qbase = ((0 * NWIN + wi) * HEADS + head) << 11;
    int kbase = ((1 * NWIN + wi) * HEADS + head) << 11;
    int vbase = ((2 * NWIN + wi) * HEADS + head) << 11;

#pragma unroll
    for (int r = 0; r < 8; r++) {
        int p = tid + 256 * r;
        sQ[p] = g_qkv[qbase + p];
        sV[p] = g_qkv[vbase + p];
        float kv = g_qkv[kbase + p];
        sKT[p & 31][p >> 5] = kv;   // transposed K
    }
    if (tid < 64) {
        int Hb = (wi >> 6) & 7, Wb = (wi >> 3) & 7, Db = wi & 7;
        int ih = tid >> 4, iw = (tid >> 2) & 3, id = tid & 3;
        int rh = (Hb == 7) ? (ih >= 2 ? 2 : 1) : 0;
        int rw = (Wb == 7) ? (iw >= 2 ? 2 : 1) : 0;
        int rd = (Db == 7) ? (id >= 2 ? 2 : 1) : 0;
        sReg[tid] = (unsigned char)(rh * 9 + rw * 3 + rd);
    }
    for (int idx = tid; idx < 343; idx += 256) sBias[idx] = bias_table[idx * HEADS + head];
    __syncthreads();

    // scores: 16x16 thread grid, 4x4 per thread
    int tx = tid & 15, ty = tid >> 4;
    float acc[4][4];
#pragma unroll
    for (int i = 0; i < 4; i++)
#pragma unroll
        for (int j = 0; j < 4; j++) acc[i][j] = 0.f;
#pragma unroll
    for (int d = 0; d < 32; d++) {
        float a[4];
#pragma unroll
        for (int i = 0; i < 4; i++) a[i] = sQ[(ty * 4 + i) * 32 + d];
        float4 b4 = *(float4*)&sKT[d][tx * 4];
        float b[4] = {b4.x, b4.y, b4.z, b4.w};
#pragma unroll
        for (int i = 0; i < 4; i++)
#pragma unroll
            for (int j = 0; j < 4; j++) acc[i][j] += a[i] * b[j];
    }
    const float scale = 0.17677669529663687f;   // 32^-0.5
#pragma unroll
    for (int ii = 0; ii < 4; ii++) {
        int i = ty * 4 + ii;
        int ih = i >> 4, iw = (i >> 2) & 3, idd = i & 3;
#pragma unroll
        for (int jj = 0; jj < 4; jj++) {
            int j = tx * 4 + jj;
            int jh = j >> 4, jw = (j >> 2) & 3, jd = j & 3;
            int rel = ((ih - jh + 3) * 7 + (iw - jw + 3)) * 7 + (idd - jd + 3);
            float s = acc[ii][jj] * scale + sBias[rel];
            if (sReg[i] != sReg[j]) s -= 100.0f;
            sS[i][j] = s;
        }
    }
    __syncthreads();

    // softmax: 4 threads per row, 16 cols each (lanes 4g..4g+3 in-warp)
    {
        int row = tid >> 2, g = tid & 3;
        float m = -1e30f;
        float e[16];
#pragma unroll
        for (int c = 0; c < 16; c++) m = fmaxf(m, sS[row][g * 16 + c]);
        m = fmaxf(m, __shfl_xor_sync(0xffffffffu, m, 1));
        m = fmaxf(m, __shfl_xor_sync(0xffffffffu, m, 2));
        float sum = 0.f;
#pragma unroll
        for (int c = 0; c < 16; c++) { e[c] = expf(sS[row][g * 16 + c] - m); sum += e[c]; }
        sum += __shfl_xor_sync(0xffffffffu, sum, 1);
        sum += __shfl_xor_sync(0xffffffffu, sum, 2);
        float inv = 1.0f / sum;
#pragma unroll
        for (int c = 0; c < 16; c++) sS[row][g * 16 + c] = e[c] * inv;
    }
    __syncthreads();

    // out = P @ V : lane d = tid&31 handles 8 rows
    {
        int d = tid & 31;
        int i0 = (tid >> 5) * 8;
#pragma unroll
        for (int i = i0; i < i0 + 8; i++) {
            float o = 0.f;
#pragma unroll
            for (int j = 0; j < 64; j++) o += sS[i][j] * sV[j * 32 + d];
            g_attnout[(size_t)(wi * 64 + i) * C_DIM + head * 32 + d] = o;
        }
    }
}

extern "C" void kernel_launch(void* const* d_in, const int* in_sizes, int n_in,
                              void* d_out, int out_size) {
    const float* x          = (const float*)d_in[0];
    const float* g1         = (const float*)d_in[1];
    const float* b1         = (const float*)d_in[2];
    const float* wqkv       = (const float*)d_in[3];
    const float* bqkv       = (const float*)d_in[4];
    const float* wo         = (const float*)d_in[5];
    const float* bo         = (const float*)d_in[6];
    const float* bias_table = (const float*)d_in[7];
    const float* g2         = (const float*)d_in[8];
    const float* b2         = (const float*)d_in[9];
    const float* w1         = (const float*)d_in[10];
    const float* bm1        = (const float*)d_in[11];
    const float* w2         = (const float*)d_in[12];
    const float* bm2        = (const float*)d_in[13];
    float* out              = (float*)d_out;

    // 1. LN1 + shift + window partition
    ln_kernel<<<M_TOT / 8, 256>>>(x, g1, b1, 0);
    // 2. QKV projection (+scatter to [3][win][head][n][hd])
    gemm_kernel<<<dim3(576 / 64, M_TOT / 64), 256>>>(wqkv, bqkv, nullptr, nullptr, C_DIM, 576, 0);
    // 3. windowed attention
    attn_kernel<<<NWIN * HEADS, 256>>>(bias_table);
    // 4. output projection + reverse shift + residual -> xo (original layout)
    gemm_kernel<<<dim3(192 / 64, M_TOT / 64), 256>>>(wo, bo, x, nullptr, C_DIM, C_DIM, 1);
    // 5. LN2
    ln_kernel<<<M_TOT / 8, 256>>>(nullptr, g2, b2, 1);
    // 6. fc1 + gelu
    gemm_kernel<<<dim3(768 / 64, M_TOT / 64), 256>>>(w1, bm1, nullptr, nullptr, C_DIM, HID, 2);
    // 7. fc2 + residual -> out
    gemm_kernel<<<dim3(192 / 64, M_TOT / 64), 256>>>(w2, bm2, nullptr, out, HID, C_DIM, 3);
}

// round 5
// speedup vs baseline: 2.2671x; 2.2671x over previous
#include <cuda_runtime.h>
#include <cuda_bf16.h>
#include <math.h>
#include <stdint.h>

// ---------------- problem constants ----------------
#define BATCH 2
#define GRID_DIM 32         // H = W = D = 32
#define C_DIM 192
#define HEADS 6
#define HD 32               // head dim
#define NTOK 64             // tokens per 4x4x4 window
#define NWIN 1024           // B * (32/4)^3
#define M_TOT (NWIN * NTOK) // 65536 rows
#define HID 768
#define SHIFT_AMT 2

// ---------------- scratch (device globals; no allocs) ----------------
__device__ float g_xw[M_TOT * C_DIM];        // LN1 + shifted + window-partitioned
__device__ float g_qkv[3 * NWIN * HEADS * NTOK * HD];
__device__ float g_attnout[M_TOT * C_DIM];   // window layout [wi][n][c]
__device__ float g_xo[M_TOT * C_DIM];        // original layout, residual added
__device__ float g_xn2[M_TOT * C_DIM];       // LN2(xo)
__device__ float g_h1[M_TOT * HID];          // gelu(fc1)

// ---------------- helpers ----------------
__device__ __forceinline__ float gelu_exact(float v) {
    return 0.5f * v * (1.0f + erff(v * 0.70710678118654752f));
}

__device__ __forceinline__ uint32_t f2tf32(float f) {
    uint32_t r;
    asm("cvt.rna.tf32.f32 %0, %1;" : "=r"(r) : "f"(f));
    return r;
}

__device__ __forceinline__ void mma_tf32(float (&c)[4], const uint32_t (&a)[4],
                                         const uint32_t (&b)[2]) {
    asm volatile(
        "mma.sync.aligned.m16n8k8.row.col.f32.tf32.tf32.f32 "
        "{%0,%1,%2,%3}, {%4,%5,%6,%7}, {%8,%9}, {%0,%1,%2,%3};"
        : "+f"(c[0]), "+f"(c[1]), "+f"(c[2]), "+f"(c[3])
        : "r"(a[0]), "r"(a[1]), "r"(a[2]), "r"(a[3]), "r"(b[0]), "r"(b[1]));
}

// Map window-layout row t -> original-layout flat token index.
__device__ __forceinline__ int winrow_to_orig(int t) {
    int wi = t >> 6, n = t & 63;
    int b  = wi >> 9;
    int Hb = (wi >> 6) & 7, Wb = (wi >> 3) & 7, Db = wi & 7;
    int i = n >> 4, j = (n >> 2) & 3, k = n & 3;
    int h = ((Hb << 2) + i + SHIFT_AMT) & 31;
    int w = ((Wb << 2) + j + SHIFT_AMT) & 31;
    int d = ((Db << 2) + k + SHIFT_AMT) & 31;
    return (((b * 32 + h) * 32 + w) * 32 + d);
}

// ---------------- LN kernels (warp per token) ----------------
__global__ __launch_bounds__(256) void ln_kernel(const float* __restrict__ xin,
                                                 const float* __restrict__ gma,
                                                 const float* __restrict__ bta,
                                                 int mode) {
    int warp = threadIdx.x >> 5, lane = threadIdx.x & 31;
    int t = blockIdx.x * 8 + warp;
    const float* src;
    float* dst;
    if (mode == 0) {
        src = xin + (size_t)winrow_to_orig(t) * C_DIM;
        dst = g_xw + (size_t)t * C_DIM;
    } else {
        src = g_xo + (size_t)t * C_DIM;
        dst = g_xn2 + (size_t)t * C_DIM;
    }
    float v[6];
    float s = 0.f;
#pragma unroll
    for (int k = 0; k < 6; k++) { v[k] = src[lane + 32 * k]; s += v[k]; }
#pragma unroll
    for (int o = 16; o > 0; o >>= 1) s += __shfl_xor_sync(0xffffffffu, s, o);
    float mean = s * (1.0f / C_DIM);
    float q = 0.f;
#pragma unroll
    for (int k = 0; k < 6; k++) { float d = v[k] - mean; q += d * d; }
#pragma unroll
    for (int o = 16; o > 0; o >>= 1) q += __shfl_xor_sync(0xffffffffu, q, o);
    float rstd = rsqrtf(q * (1.0f / C_DIM) + 1e-5f);
#pragma unroll
    for (int k = 0; k < 6; k++) {
        int c = lane + 32 * k;
        dst[c] = (v[k] - mean) * rstd * gma[c] + bta[c];
    }
}

// ---------------- tf32 tensor-core GEMM ----------------
// Block tile 128x64, k-step 32, 256 threads = 8 warps (4x2), warp tile 32x32.
// mode 0: A=g_xw   [M,192] @ wqkv[192,576] + bqkv -> scatter into g_qkv
// mode 1: A=g_attnout[M,192] @ wo[192,192] + bo, +residual x (permuted) -> g_xo
// mode 2: A=g_xn2  [M,192] @ w1[192,768] + bm1, gelu -> g_h1
// mode 3: A=g_h1   [M,768] @ w2[768,192] + bm2, + g_xo -> dout
__global__ __launch_bounds__(256) void gemm_tf32(const float* __restrict__ Bw,
                                                 const float* __restrict__ bias,
                                                 const float* __restrict__ xres,
                                                 float* __restrict__ dout,
                                                 int K, int N, int mode) {
    const float* A = (mode == 0) ? g_xw
                   : (mode == 1) ? g_attnout
                   : (mode == 2) ? g_xn2
                                 : g_h1;
    __shared__ uint32_t As[128 * 36];   // [m][k] pad 36
    __shared__ uint32_t Bs[32 * 72];    // [k][n] pad 72

    int tid = threadIdx.x;
    int warp = tid >> 5, lane = tid & 31;
    int gid = lane >> 2, tig = lane & 3;
    int warpM = warp & 3, warpN = warp >> 2;
    int row0 = blockIdx.y * 128, col0 = blockIdx.x * 64;

    // global load coordinates
    int arow = tid >> 3, acol = (tid & 7) * 4;      // A: 4 x float4 (rows arow+32i)
    int brow = tid >> 4, bcol = (tid & 15) * 4;     // B: 2 x float4 (rows brow+16i)

    float acc[2][4][4];
#pragma unroll
    for (int mt = 0; mt < 2; mt++)
#pragma unroll
        for (int nt = 0; nt < 4; nt++)
#pragma unroll
            for (int i = 0; i < 4; i++) acc[mt][nt][i] = 0.f;

    float4 aReg[4], bReg[2];
    // prologue: load k0 = 0
#pragma unroll
    for (int i = 0; i < 4; i++)
        aReg[i] = *(const float4*)&A[(size_t)(row0 + arow + 32 * i) * K + acol];
#pragma unroll
    for (int i = 0; i < 2; i++)
        bReg[i] = *(const float4*)&Bw[(size_t)(brow + 16 * i) * N + col0 + bcol];
#pragma unroll
    for (int i = 0; i < 4; i++) {
        uint32_t* p = &As[(arow + 32 * i) * 36 + acol];
        p[0] = f2tf32(aReg[i].x); p[1] = f2tf32(aReg[i].y);
        p[2] = f2tf32(aReg[i].z); p[3] = f2tf32(aReg[i].w);
    }
#pragma unroll
    for (int i = 0; i < 2; i++) {
        uint32_t* p = &Bs[(brow + 16 * i) * 72 + bcol];
        p[0] = f2tf32(bReg[i].x); p[1] = f2tf32(bReg[i].y);
        p[2] = f2tf32(bReg[i].z); p[3] = f2tf32(bReg[i].w);
    }

    for (int k0 = 0;;) {
        __syncthreads();
        bool more = (k0 + 32 < K);
        if (more) {
#pragma unroll
            for (int i = 0; i < 4; i++)
                aReg[i] = *(const float4*)&A[(size_t)(row0 + arow + 32 * i) * K + k0 + 32 + acol];
#pragma unroll
            for (int i = 0; i < 2; i++)
                bReg[i] = *(const float4*)&Bw[(size_t)(k0 + 32 + brow + 16 * i) * N + col0 + bcol];
        }
        // compute 4 sub-steps of k=8
#pragma unroll
        for (int kk = 0; kk < 4; kk++) {
            int k8 = kk * 8;
            uint32_t afr[2][4];
#pragma unroll
            for (int mt = 0; mt < 2; mt++) {
                int m = warpM * 32 + mt * 16 + gid;
                afr[mt][0] = As[m * 36 + k8 + tig];
                afr[mt][1] = As[(m + 8) * 36 + k8 + tig];
                afr[mt][2] = As[m * 36 + k8 + tig + 4];
                afr[mt][3] = As[(m + 8) * 36 + k8 + tig + 4];
            }
            uint32_t bfr[4][2];
#pragma unroll
            for (int nt = 0; nt < 4; nt++) {
                int n = warpN * 32 + nt * 8 + gid;
                bfr[nt][0] = Bs[(k8 + tig) * 72 + n];
                bfr[nt][1] = Bs[(k8 + tig + 4) * 72 + n];
            }
#pragma unroll
            for (int mt = 0; mt < 2; mt++)
#pragma unroll
                for (int nt = 0; nt < 4; nt++)
                    mma_tf32(acc[mt][nt], afr[mt], bfr[nt]);
        }
        k0 += 32;
        if (!more) break;
        __syncthreads();
#pragma unroll
        for (int i = 0; i < 4; i++) {
            uint32_t* p = &As[(arow + 32 * i) * 36 + acol];
            p[0] = f2tf32(aReg[i].x); p[1] = f2tf32(aReg[i].y);
            p[2] = f2tf32(aReg[i].z); p[3] = f2tf32(aReg[i].w);
        }
#pragma unroll
        for (int i = 0; i < 2; i++) {
            uint32_t* p = &Bs[(brow + 16 * i) * 72 + bcol];
            p[0] = f2tf32(bReg[i].x); p[1] = f2tf32(bReg[i].y);
            p[2] = f2tf32(bReg[i].z); p[3] = f2tf32(bReg[i].w);
        }
    }

    // epilogue: each thread owns rows (r, r+8) x col pairs (c, c+1)
#pragma unroll
    for (int mt = 0; mt < 2; mt++) {
        int rbase = row0 + warpM * 32 + mt * 16 + gid;
#pragma unroll
        for (int half = 0; half < 2; half++) {
            int row = rbase + half * 8;
            int obase1 = 0;
            if (mode == 1) obase1 = winrow_to_orig(row) * C_DIM;
#pragma unroll
            for (int nt = 0; nt < 4; nt++) {
                int col = col0 + warpN * 32 + nt * 8 + 2 * tig;
                float v0 = acc[mt][nt][half * 2 + 0] + bias[col];
                float v1 = acc[mt][nt][half * 2 + 1] + bias[col + 1];
                if (mode == 0) {
                    int wi = row >> 6, n = row & 63;
                    int which = col / 192;
                    int rem = col - which * 192;
                    int head = rem >> 5, hdi = rem & 31;
                    float* p = &g_qkv[(((which * NWIN + wi) * HEADS + head) << 11) + (n << 5) + hdi];
                    *(float2*)p = make_float2(v0, v1);
                } else if (mode == 1) {
                    float* p = &g_xo[obase1 + col];
                    const float* r = &xres[obase1 + col];
                    *(float2*)p = make_float2(v0 + r[0], v1 + r[1]);
                } else if (mode == 2) {
                    float* p = &g_h1[(size_t)row * HID + col];
                    *(float2*)p = make_float2(gelu_exact(v0), gelu_exact(v1));
                } else {
                    size_t o = (size_t)row * C_DIM + col;
                    *(float2*)&dout[o] = make_float2(v0 + g_xo[o], v1 + g_xo[o + 1]);
                }
            }
        }
    }
}

// ---------------- attention: one block per (window, head) ----------------
__global__ __launch_bounds__(256) void attn_kernel(const float* __restrict__ bias_table) {
    __shared__ float sQ[NTOK * HD];
    __shared__ float sKT[32][68];
    __shared__ float sV[NTOK * HD];
    __shared__ float sS[64][65];
    __shared__ float sBias[343];
    __shared__ unsigned char sReg[64];

    int wi = blockIdx.x / HEADS, head = blockIdx.x % HEADS;
    int tid = threadIdx.x;

    int qbase = ((0 * NWIN + wi) * HEADS + head) << 11;
    int kbase = ((1 * NWIN + wi) * HEADS + head) << 11;
    int vbase = ((2 * NWIN + wi) * HEADS + head) << 11;

#pragma unroll
    for (int r = 0; r < 8; r++) {
        int p = tid + 256 * r;
        sQ[p] = g_qkv[qbase + p];
        sV[p] = g_qkv[vbase + p];
        float kv = g_qkv[kbase + p];
        sKT[p & 31][p >> 5] = kv;
    }
    if (tid < 64) {
        int Hb = (wi >> 6) & 7, Wb = (wi >> 3) & 7, Db = wi & 7;
        int ih = tid >> 4, iw = (tid >> 2) & 3, id = tid & 3;
        int rh = (Hb == 7) ? (ih >= 2 ? 2 : 1) : 0;
        int rw = (Wb == 7) ? (iw >= 2 ? 2 : 1) : 0;
        int rd = (Db == 7) ? (id >= 2 ? 2 : 1) : 0;
        sReg[tid] = (unsigned char)(rh * 9 + rw * 3 + rd);
    }
    for (int idx = tid; idx < 343; idx += 256) sBias[idx] = bias_table[idx * HEADS + head];
    __syncthreads();

    int tx = tid & 15, ty = tid >> 4;
    float acc[4][4];
#pragma unroll
    for (int i = 0; i < 4; i++)
#pragma unroll
        for (int j = 0; j < 4; j++) acc[i][j] = 0.f;
#pragma unroll
    for (int d = 0; d < 32; d++) {
        float a[4];
#pragma unroll
        for (int i = 0; i < 4; i++) a[i] = sQ[(ty * 4 + i) * 32 + d];
        float4 b4 = *(float4*)&sKT[d][tx * 4];
        float b[4] = {b4.x, b4.y, b4.z, b4.w};
#pragma unroll
        for (int i = 0; i < 4; i++)
#pragma unroll
            for (int j = 0; j < 4; j++) acc[i][j] += a[i] * b[j];
    }
    const float scale = 0.17677669529663687f;
#pragma unroll
    for (int ii = 0; ii < 4; ii++) {
        int i = ty * 4 + ii;
        int ih = i >> 4, iw = (i >> 2) & 3, idd = i & 3;
#pragma unroll
        for (int jj = 0; jj < 4; jj++) {
            int j = tx * 4 + jj;
            int jh = j >> 4, jw = (j >> 2) & 3, jd = j & 3;
            int rel = ((ih - jh + 3) * 7 + (iw - jw + 3)) * 7 + (idd - jd + 3);
            float s = acc[ii][jj] * scale + sBias[rel];
            if (sReg[i] != sReg[j]) s -= 100.0f;
            sS[i][j] = s;
        }
    }
    __syncthreads();

    {
        int row = tid >> 2, g = tid & 3;
        float m = -1e30f;
        float e[16];
#pragma unroll
        for (int c = 0; c < 16; c++) m = fmaxf(m, sS[row][g * 16 + c]);
        m = fmaxf(m, __shfl_xor_sync(0xffffffffu, m, 1));
        m = fmaxf(m, __shfl_xor_sync(0xffffffffu, m, 2));
        float sum = 0.f;
#pragma unroll
        for (int c = 0; c < 16; c++) { e[c] = expf(sS[row][g * 16 + c] - m); sum += e[c]; }
        sum += __shfl_xor_sync(0xffffffffu, sum, 1);
        sum += __shfl_xor_sync(0xffffffffu, sum, 2);
        float inv = 1.0f / sum;
#pragma unroll
        for (int c = 0; c < 16; c++) sS[row][g * 16 + c] = e[c] * inv;
    }
    __syncthreads();

    {
        int d = tid & 31;
        int i0 = (tid >> 5) * 8;
#pragma unroll
        for (int i = i0; i < i0 + 8; i++) {
            float o = 0.f;
#pragma unroll
            for (int j = 0; j < 64; j++) o += sS[i][j] * sV[j * 32 + d];
            g_attnout[(size_t)(wi * 64 + i) * C_DIM + head * 32 + d] = o;
        }
    }
}

extern "C" void kernel_launch(void* const* d_in, const int* in_sizes, int n_in,
                              void* d_out, int out_size) {
    const float* x          = (const float*)d_in[0];
    const float* g1         = (const float*)d_in[1];
    const float* b1         = (const float*)d_in[2];
    const float* wqkv       = (const float*)d_in[3];
    const float* bqkv       = (const float*)d_in[4];
    const float* wo         = (const float*)d_in[5];
    const float* bo         = (const float*)d_in[6];
    const float* bias_table = (const float*)d_in[7];
    const float* g2         = (const float*)d_in[8];
    const float* b2         = (const float*)d_in[9];
    const float* w1         = (const float*)d_in[10];
    const float* bm1        = (const float*)d_in[11];
    const float* w2         = (const float*)d_in[12];
    const float* bm2        = (const float*)d_in[13];
    float* out              = (float*)d_out;

    // 1. LN1 + shift + window partition
    ln_kernel<<<M_TOT / 8, 256>>>(x, g1, b1, 0);
    // 2. QKV projection (tf32 tensor cores, scatter epilogue)
    gemm_tf32<<<dim3(576 / 64, M_TOT / 128), 256>>>(wqkv, bqkv, nullptr, nullptr, C_DIM, 576, 0);
    // 3. windowed attention
    attn_kernel<<<NWIN * HEADS, 256>>>(bias_table);
    // 4. output projection + reverse shift + residual -> xo
    gemm_tf32<<<dim3(192 / 64, M_TOT / 128), 256>>>(wo, bo, x, nullptr, C_DIM, C_DIM, 1);
    // 5. LN2
    ln_kernel<<<M_TOT / 8, 256>>>(nullptr, g2, b2, 1);
    // 6. fc1 + gelu
    gemm_tf32<<<dim3(768 / 64, M_TOT / 128), 256>>>(w1, bm1, nullptr, nullptr, C_DIM, HID, 2);
    // 7. fc2 + residual -> out
    gemm_tf32<<<dim3(192 / 64, M_TOT / 128), 256>>>(w2, bm2, nullptr, out, HID, C_DIM, 3);
}

// round 7
// speedup vs baseline: 2.2835x; 1.0072x over previous
#include <cuda_runtime.h>
#include <cuda_bf16.h>
#include <math.h>
#include <stdint.h>

// ---------------- problem constants ----------------
#define BATCH 2
#define GRID_DIM 32         // H = W = D = 32
#define C_DIM 192
#define HEADS 6
#define HD 32               // head dim
#define NTOK 64             // tokens per 4x4x4 window
#define NWIN 1024           // B * (32/4)^3
#define M_TOT (NWIN * NTOK) // 65536 rows
#define HID 768
#define SHIFT_AMT 2

// ---------------- scratch (device globals; no allocs) ----------------
__device__ __nv_bfloat16 g_xw[M_TOT * C_DIM];      // LN1+shift+win-part (GEMM A)
__device__ float         g_qkv[3 * NWIN * HEADS * NTOK * HD];  // fp32 for attn
__device__ __nv_bfloat16 g_attnout[M_TOT * C_DIM]; // window layout (GEMM A)
__device__ float         g_xo[M_TOT * C_DIM];      // residual stream, fp32
__device__ __nv_bfloat16 g_xn2[M_TOT * C_DIM];     // LN2 out (GEMM A)
__device__ __nv_bfloat16 g_h1[M_TOT * HID];        // gelu(fc1) (GEMM A)

// ---------------- helpers ----------------
__device__ __forceinline__ float gelu_exact(float v) {
    return 0.5f * v * (1.0f + erff(v * 0.70710678118654752f));
}

__device__ __forceinline__ void mma_bf16(float (&c)[4], const uint32_t (&a)[4],
                                         const uint32_t (&b)[2]) {
    asm volatile(
        "mma.sync.aligned.m16n8k16.row.col.f32.bf16.bf16.f32 "
        "{%0,%1,%2,%3}, {%4,%5,%6,%7}, {%8,%9}, {%0,%1,%2,%3};"
        : "+f"(c[0]), "+f"(c[1]), "+f"(c[2]), "+f"(c[3])
        : "r"(a[0]), "r"(a[1]), "r"(a[2]), "r"(a[3]), "r"(b[0]), "r"(b[1]));
}

// Map window-layout row t -> original-layout flat token index.
__device__ __forceinline__ int winrow_to_orig(int t) {
    int wi = t >> 6, n = t & 63;
    int b  = wi >> 9;
    int Hb = (wi >> 6) & 7, Wb = (wi >> 3) & 7, Db = wi & 7;
    int i = n >> 4, j = (n >> 2) & 3, k = n & 3;
    int h = ((Hb << 2) + i + SHIFT_AMT) & 31;
    int w = ((Wb << 2) + j + SHIFT_AMT) & 31;
    int d = ((Db << 2) + k + SHIFT_AMT) & 31;
    return (((b * 32 + h) * 32 + w) * 32 + d);
}

// ---------------- LN kernels (warp per token), bf16 output ----------------
__global__ __launch_bounds__(256) void ln_kernel(const float* __restrict__ xin,
                                                 const float* __restrict__ gma,
                                                 const float* __restrict__ bta,
                                                 int mode) {
    int warp = threadIdx.x >> 5, lane = threadIdx.x & 31;
    int t = blockIdx.x * 8 + warp;
    const float* src;
    __nv_bfloat16* dst;
    if (mode == 0) {
        src = xin + (size_t)winrow_to_orig(t) * C_DIM;
        dst = g_xw + (size_t)t * C_DIM;
    } else {
        src = g_xo + (size_t)t * C_DIM;
        dst = g_xn2 + (size_t)t * C_DIM;
    }
    float v[6];
    float s = 0.f;
#pragma unroll
    for (int k = 0; k < 6; k++) { v[k] = src[lane + 32 * k]; s += v[k]; }
#pragma unroll
    for (int o = 16; o > 0; o >>= 1) s += __shfl_xor_sync(0xffffffffu, s, o);
    float mean = s * (1.0f / C_DIM);
    float q = 0.f;
#pragma unroll
    for (int k = 0; k < 6; k++) { float d = v[k] - mean; q += d * d; }
#pragma unroll
    for (int o = 16; o > 0; o >>= 1) q += __shfl_xor_sync(0xffffffffu, q, o);
    float rstd = rsqrtf(q * (1.0f / C_DIM) + 1e-5f);
#pragma unroll
    for (int k = 0; k < 6; k++) {
        int c = lane + 32 * k;
        dst[c] = __float2bfloat16((v[k] - mean) * rstd * gma[c] + bta[c]);
    }
}

// ---------------- bf16 tensor-core GEMM ----------------
// Block tile 128x64, k-step 32, 256 threads = 8 warps (4x2), warp tile 32x32.
// A (bf16 gmem): mode 0 g_xw, 1 g_attnout, 2 g_xn2, 3 g_h1
// smem strides padded to 40 bf16 (20 banks) -> conflict-free fragment loads.
__global__ __launch_bounds__(256) void gemm_bf16(const float* __restrict__ Bw,
                                                 const float* __restrict__ bias,
                                                 const float* __restrict__ xres,
                                                 float* __restrict__ dout,
                                                 int K, int N, int mode) {
    const __nv_bfloat16* A = (mode == 0) ? g_xw
                           : (mode == 1) ? g_attnout
                           : (mode == 2) ? g_xn2
                                         : g_h1;
    __shared__ __nv_bfloat16 AsH[128 * 40];   // [m][k], stride 40
    __shared__ __nv_bfloat16 BsH[64 * 40];    // [n][k] (transposed), stride 40

    int tid = threadIdx.x;
    int warp = tid >> 5, lane = tid & 31;
    int gid = lane >> 2, tig = lane & 3;
    int warpM = warp & 3, warpN = warp >> 2;
    int row0 = blockIdx.y * 128, col0 = blockIdx.x * 64;

    // global load coordinates
    int arow = tid >> 2, acol = (tid & 3) * 8;      // A: 2 x uint4 (rows arow, arow+64)
    int brow = tid >> 4, bcol = (tid & 15) * 4;     // B: 2 x float4 (rows brow, brow+16)

    float acc[2][4][4];
#pragma unroll
    for (int mt = 0; mt < 2; mt++)
#pragma unroll
        for (int nt = 0; nt < 4; nt++)
#pragma unroll
            for (int i = 0; i < 4; i++) acc[mt][nt][i] = 0.f;

    uint4 aReg[2];
    float4 bReg[2];
#pragma unroll
    for (int i = 0; i < 2; i++)
        aReg[i] = *(const uint4*)&A[(size_t)(row0 + arow + 64 * i) * K + acol];
#pragma unroll
    for (int i = 0; i < 2; i++)
        bReg[i] = *(const float4*)&Bw[(size_t)(brow + 16 * i) * N + col0 + bcol];

#pragma unroll
    for (int i = 0; i < 2; i++) {
        uint32_t* p = (uint32_t*)&AsH[(arow + 64 * i) * 40 + acol];
        p[0] = aReg[i].x; p[1] = aReg[i].y; p[2] = aReg[i].z; p[3] = aReg[i].w;
    }
#pragma unroll
    for (int i = 0; i < 2; i++) {
        int kk = brow + 16 * i;
        BsH[(bcol + 0) * 40 + kk] = __float2bfloat16(bReg[i].x);
        BsH[(bcol + 1) * 40 + kk] = __float2bfloat16(bReg[i].y);
        BsH[(bcol + 2) * 40 + kk] = __float2bfloat16(bReg[i].z);
        BsH[(bcol + 3) * 40 + kk] = __float2bfloat16(bReg[i].w);
    }

    for (int k0 = 0;;) {
        __syncthreads();
        bool more = (k0 + 32 < K);
        if (more) {
#pragma unroll
            for (int i = 0; i < 2; i++)
                aReg[i] = *(const uint4*)&A[(size_t)(row0 + arow + 64 * i) * K + k0 + 32 + acol];
#pragma unroll
            for (int i = 0; i < 2; i++)
                bReg[i] = *(const float4*)&Bw[(size_t)(k0 + 32 + brow + 16 * i) * N + col0 + bcol];
        }
        // two k16 sub-steps
#pragma unroll
        for (int kk = 0; kk < 32; kk += 16) {
            uint32_t afr[2][4];
#pragma unroll
            for (int mt = 0; mt < 2; mt++) {
                int m = warpM * 32 + mt * 16 + gid;
                afr[mt][0] = *(const uint32_t*)&AsH[m * 40 + kk + 2 * tig];
                afr[mt][1] = *(const uint32_t*)&AsH[(m + 8) * 40 + kk + 2 * tig];
                afr[mt][2] = *(const uint32_t*)&AsH[m * 40 + kk + 8 + 2 * tig];
                afr[mt][3] = *(const uint32_t*)&AsH[(m + 8) * 40 + kk + 8 + 2 * tig];
            }
            uint32_t bfr[4][2];
#pragma unroll
            for (int nt = 0; nt < 4; nt++) {
                int n = warpN * 32 + nt * 8 + gid;
                bfr[nt][0] = *(const uint32_t*)&BsH[n * 40 + kk + 2 * tig];
                bfr[nt][1] = *(const uint32_t*)&BsH[n * 40 + kk + 8 + 2 * tig];
            }
#pragma unroll
            for (int mt = 0; mt < 2; mt++)
#pragma unroll
                for (int nt = 0; nt < 4; nt++)
                    mma_bf16(acc[mt][nt], afr[mt], bfr[nt]);
        }
        k0 += 32;
        if (!more) break;
        __syncthreads();
#pragma unroll
        for (int i = 0; i < 2; i++) {
            uint32_t* p = (uint32_t*)&AsH[(arow + 64 * i) * 40 + acol];
            p[0] = aReg[i].x; p[1] = aReg[i].y; p[2] = aReg[i].z; p[3] = aReg[i].w;
        }
#pragma unroll
        for (int i = 0; i < 2; i++) {
            int kk = brow + 16 * i;
            BsH[(bcol + 0) * 40 + kk] = __float2bfloat16(bReg[i].x);
            BsH[(bcol + 1) * 40 + kk] = __float2bfloat16(bReg[i].y);
            BsH[(bcol + 2) * 40 + kk] = __float2bfloat16(bReg[i].z);
            BsH[(bcol + 3) * 40 + kk] = __float2bfloat16(bReg[i].w);
        }
    }

    // epilogue: each thread owns rows (r, r+8) x col pairs (c, c+1)
#pragma unroll
    for (int mt = 0; mt < 2; mt++) {
        int rbase = row0 + warpM * 32 + mt * 16 + gid;
#pragma unroll
        for (int half = 0; half < 2; half++) {
            int row = rbase + half * 8;
            int obase1 = 0;
            if (mode == 1) obase1 = winrow_to_orig(row) * C_DIM;
#pragma unroll
            for (int nt = 0; nt < 4; nt++) {
                int col = col0 + warpN * 32 + nt * 8 + 2 * tig;
                float v0 = acc[mt][nt][half * 2 + 0] + bias[col];
                float v1 = acc[mt][nt][half * 2 + 1] + bias[col + 1];
                if (mode == 0) {
                    int wi = row >> 6, n = row & 63;
                    int which = col / 192;
                    int rem = col - which * 192;
                    int head = rem >> 5, hdi = rem & 31;
                    float* p = &g_qkv[(((which * NWIN + wi) * HEADS + head) << 11) + (n << 5) + hdi];
                    *(float2*)p = make_float2(v0, v1);
                } else if (mode == 1) {
                    float* p = &g_xo[obase1 + col];
                    const float* r = &xres[obase1 + col];
                    *(float2*)p = make_float2(v0 + r[0], v1 + r[1]);
                } else if (mode == 2) {
                    __nv_bfloat162* p = (__nv_bfloat162*)&g_h1[(size_t)row * HID + col];
                    *p = __floats2bfloat162_rn(gelu_exact(v0), gelu_exact(v1));
                } else {
                    size_t o = (size_t)row * C_DIM + col;
                    *(float2*)&dout[o] = make_float2(v0 + g_xo[o], v1 + g_xo[o + 1]);
                }
            }
        }
    }
}

// ---------------- attention: one block per (window, head) ----------------
__global__ __launch_bounds__(256) void attn_kernel(const float* __restrict__ bias_table) {
    __shared__ float sQ[NTOK * HD];
    __shared__ float sKT[32][68];
    __shared__ float sV[NTOK * HD];
    __shared__ float sS[64][65];
    __shared__ float sBias[343];
    __shared__ unsigned char sReg[64];

    int wi = blockIdx.x / HEADS, head = blockIdx.x % HEADS;
    int tid = threadIdx.x;

    int qbase = ((0 * NWIN + wi) * HEADS + head) << 11;
    int kbase = ((1 * NWIN + wi) * HEADS + head) << 11;
    int vbase = ((2 * NWIN + wi) * HEADS + head) << 11;

#pragma unroll
    for (int r = 0; r < 8; r++) {
        int p = tid + 256 * r;
        sQ[p] = g_qkv[qbase + p];
        sV[p] = g_qkv[vbase + p];
        float kv = g_qkv[kbase + p];
        sKT[p & 31][p >> 5] = kv;
    }
    if (tid < 64) {
        int Hb = (wi >> 6) & 7, Wb = (wi >> 3) & 7, Db = wi & 7;
        int ih = tid >> 4, iw = (tid >> 2) & 3, id = tid & 3;
        int rh = (Hb == 7) ? (ih >= 2 ? 2 : 1) : 0;
        int rw = (Wb == 7) ? (iw >= 2 ? 2 : 1) : 0;
        int rd = (Db == 7) ? (id >= 2 ? 2 : 1) : 0;
        sReg[tid] = (unsigned char)(rh * 9 + rw * 3 + rd);
    }
    for (int idx = tid; idx < 343; idx += 256) sBias[idx] = bias_table[idx * HEADS + head];
    __syncthreads();

    int tx = tid & 15, ty = tid >> 4;
    float acc[4][4];
#pragma unroll
    for (int i = 0; i < 4; i++)
#pragma unroll
        for (int j = 0; j < 4; j++) acc[i][j] = 0.f;
#pragma unroll
    for (int d = 0; d < 32; d++) {
        float a[4];
#pragma unroll
        for (int i = 0; i < 4; i++) a[i] = sQ[(ty * 4 + i) * 32 + d];
        float4 b4 = *(float4*)&sKT[d][tx * 4];
        float b[4] = {b4.x, b4.y, b4.z, b4.w};
#pragma unroll
        for (int i = 0; i < 4; i++)
#pragma unroll
            for (int j = 0; j < 4; j++) acc[i][j] += a[i] * b[j];
    }
    const float scale = 0.17677669529663687f;
#pragma unroll
    for (int ii = 0; ii < 4; ii++) {
        int i = ty * 4 + ii;
        int ih = i >> 4, iw = (i >> 2) & 3, idd = i & 3;
#pragma unroll
        for (int jj = 0; jj < 4; jj++) {
            int j = tx * 4 + jj;
            int jh = j >> 4, jw = (j >> 2) & 3, jd = j & 3;
            int rel = ((ih - jh + 3) * 7 + (iw - jw + 3)) * 7 + (idd - jd + 3);
            float s = acc[ii][jj] * scale + sBias[rel];
            if (sReg[i] != sReg[j]) s -= 100.0f;
            sS[i][j] = s;
        }
    }
    __syncthreads();

    {
        int row = tid >> 2, g = tid & 3;
        float m = -1e30f;
        float e[16];
#pragma unroll
        for (int c = 0; c < 16; c++) m = fmaxf(m, sS[row][g * 16 + c]);
        m = fmaxf(m, __shfl_xor_sync(0xffffffffu, m, 1));
        m = fmaxf(m, __shfl_xor_sync(0xffffffffu, m, 2));
        float sum = 0.f;
#pragma unroll
        for (int c = 0; c < 16; c++) { e[c] = expf(sS[row][g * 16 + c] - m); sum += e[c]; }
        sum += __shfl_xor_sync(0xffffffffu, sum, 1);
        sum += __shfl_xor_sync(0xffffffffu, sum, 2);
        float inv = 1.0f / sum;
#pragma unroll
        for (int c = 0; c < 16; c++) sS[row][g * 16 + c] = e[c] * inv;
    }
    __syncthreads();

    {
        int d = tid & 31;
        int i0 = (tid >> 5) * 8;
#pragma unroll
        for (int i = i0; i < i0 + 8; i++) {
            float o = 0.f;
#pragma unroll
            for (int j = 0; j < 64; j++) o += sS[i][j] * sV[j * 32 + d];
            g_attnout[(size_t)(wi * 64 + i) * C_DIM + head * 32 + d] = __float2bfloat16(o);
        }
    }
}

extern "C" void kernel_launch(void* const* d_in, const int* in_sizes, int n_in,
                              void* d_out, int out_size) {
    const float* x          = (const float*)d_in[0];
    const float* g1         = (const float*)d_in[1];
    const float* b1         = (const float*)d_in[2];
    const float* wqkv       = (const float*)d_in[3];
    const float* bqkv       = (const float*)d_in[4];
    const float* wo         = (const float*)d_in[5];
    const float* bo         = (const float*)d_in[6];
    const float* bias_table = (const float*)d_in[7];
    const float* g2         = (const float*)d_in[8];
    const float* b2         = (const float*)d_in[9];
    const float* w1         = (const float*)d_in[10];
    const float* bm1        = (const float*)d_in[11];
    const float* w2         = (const float*)d_in[12];
    const float* bm2        = (const float*)d_in[13];
    float* out              = (float*)d_out;

    // 1. LN1 + shift + window partition (bf16 out)
    ln_kernel<<<M_TOT / 8, 256>>>(x, g1, b1, 0);
    // 2. QKV projection (bf16 mma, scatter epilogue, fp32 out)
    gemm_bf16<<<dim3(576 / 64, M_TOT / 128), 256>>>(wqkv, bqkv, nullptr, nullptr, C_DIM, 576, 0);
    // 3. windowed attention (fp32)
    attn_kernel<<<NWIN * HEADS, 256>>>(bias_table);
    // 4. output projection + reverse shift + residual -> xo (fp32)
    gemm_bf16<<<dim3(192 / 64, M_TOT / 128), 256>>>(wo, bo, x, nullptr, C_DIM, C_DIM, 1);
    // 5. LN2 (bf16 out)
    ln_kernel<<<M_TOT / 8, 256>>>(nullptr, g2, b2, 1);
    // 6. fc1 + gelu (bf16 out)
    gemm_bf16<<<dim3(768 / 64, M_TOT / 128), 256>>>(w1, bm1, nullptr, nullptr, C_DIM, HID, 2);
    // 7. fc2 + residual -> out (fp32)
    gemm_bf16<<<dim3(192 / 64, M_TOT / 128), 256>>>(w2, bm2, nullptr, out, HID, C_DIM, 3);
}

// round 8
// speedup vs baseline: 2.8203x; 1.2351x over previous
#include <cuda_runtime.h>
#include <cuda_bf16.h>
#include <math.h>
#include <stdint.h>

// ---------------- problem constants ----------------
#define BATCH 2
#define GRID_DIM 32         // H = W = D = 32
#define C_DIM 192
#define HEADS 6
#define HD 32               // head dim
#define NTOK 64             // tokens per 4x4x4 window
#define NWIN 1024           // B * (32/4)^3
#define M_TOT (NWIN * NTOK) // 65536 rows
#define HID 768
#define SHIFT_AMT 2

// ---------------- scratch (device globals; no allocs) ----------------
__device__ __nv_bfloat16 g_xw[M_TOT * C_DIM];      // LN1+shift+win-part (GEMM A)
__device__ __nv_bfloat16 g_qkv[3 * NWIN * HEADS * NTOK * HD]; // bf16, q pre-scaled
__device__ __nv_bfloat16 g_attnout[M_TOT * C_DIM]; // window layout (GEMM A)
__device__ float         g_xo[M_TOT * C_DIM];      // residual stream, fp32
__device__ __nv_bfloat16 g_xn2[M_TOT * C_DIM];     // LN2 out (GEMM A)
__device__ __nv_bfloat16 g_h1[M_TOT * HID];        // gelu(fc1) (GEMM A)

// ---------------- helpers ----------------
__device__ __forceinline__ float gelu_exact(float v) {
    return 0.5f * v * (1.0f + erff(v * 0.70710678118654752f));
}

__device__ __forceinline__ void mma_bf16(float (&c)[4], const uint32_t (&a)[4],
                                         const uint32_t (&b)[2]) {
    asm volatile(
        "mma.sync.aligned.m16n8k16.row.col.f32.bf16.bf16.f32 "
        "{%0,%1,%2,%3}, {%4,%5,%6,%7}, {%8,%9}, {%0,%1,%2,%3};"
        : "+f"(c[0]), "+f"(c[1]), "+f"(c[2]), "+f"(c[3])
        : "r"(a[0]), "r"(a[1]), "r"(a[2]), "r"(a[3]), "r"(b[0]), "r"(b[1]));
}

__device__ __forceinline__ uint32_t packbf2(float a, float b) {
    __nv_bfloat162 t = __floats2bfloat162_rn(a, b);
    return *(uint32_t*)&t;
}

// Map window-layout row t -> original-layout flat token index.
__device__ __forceinline__ int winrow_to_orig(int t) {
    int wi = t >> 6, n = t & 63;
    int b  = wi >> 9;
    int Hb = (wi >> 6) & 7, Wb = (wi >> 3) & 7, Db = wi & 7;
    int i = n >> 4, j = (n >> 2) & 3, k = n & 3;
    int h = ((Hb << 2) + i + SHIFT_AMT) & 31;
    int w = ((Wb << 2) + j + SHIFT_AMT) & 31;
    int d = ((Db << 2) + k + SHIFT_AMT) & 31;
    return (((b * 32 + h) * 32 + w) * 32 + d);
}

// ---------------- LN kernels (warp per token), bf16 output ----------------
__global__ __launch_bounds__(256) void ln_kernel(const float* __restrict__ xin,
                                                 const float* __restrict__ gma,
                                                 const float* __restrict__ bta,
                                                 int mode) {
    int warp = threadIdx.x >> 5, lane = threadIdx.x & 31;
    int t = blockIdx.x * 8 + warp;
    const float* src;
    __nv_bfloat16* dst;
    if (mode == 0) {
        src = xin + (size_t)winrow_to_orig(t) * C_DIM;
        dst = g_xw + (size_t)t * C_DIM;
    } else {
        src = g_xo + (size_t)t * C_DIM;
        dst = g_xn2 + (size_t)t * C_DIM;
    }
    float v[6];
    float s = 0.f;
#pragma unroll
    for (int k = 0; k < 6; k++) { v[k] = src[lane + 32 * k]; s += v[k]; }
#pragma unroll
    for (int o = 16; o > 0; o >>= 1) s += __shfl_xor_sync(0xffffffffu, s, o);
    float mean = s * (1.0f / C_DIM);
    float q = 0.f;
#pragma unroll
    for (int k = 0; k < 6; k++) { float d = v[k] - mean; q += d * d; }
#pragma unroll
    for (int o = 16; o > 0; o >>= 1) q += __shfl_xor_sync(0xffffffffu, q, o);
    float rstd = rsqrtf(q * (1.0f / C_DIM) + 1e-5f);
#pragma unroll
    for (int k = 0; k < 6; k++) {
        int c = lane + 32 * k;
        dst[c] = __float2bfloat16((v[k] - mean) * rstd * gma[c] + bta[c]);
    }
}

// ---------------- bf16 tensor-core GEMM ----------------
// Block tile 128x64, k-step 32, 256 threads = 8 warps (4x2), warp tile 32x32.
__global__ __launch_bounds__(256) void gemm_bf16(const float* __restrict__ Bw,
                                                 const float* __restrict__ bias,
                                                 const float* __restrict__ xres,
                                                 float* __restrict__ dout,
                                                 int K, int N, int mode) {
    const __nv_bfloat16* A = (mode == 0) ? g_xw
                           : (mode == 1) ? g_attnout
                           : (mode == 2) ? g_xn2
                                         : g_h1;
    __shared__ __nv_bfloat16 AsH[128 * 40];   // [m][k], stride 40
    __shared__ __nv_bfloat16 BsH[64 * 40];    // [n][k] (transposed), stride 40

    int tid = threadIdx.x;
    int warp = tid >> 5, lane = tid & 31;
    int gid = lane >> 2, tig = lane & 3;
    int warpM = warp & 3, warpN = warp >> 2;
    int row0 = blockIdx.y * 128, col0 = blockIdx.x * 64;

    int arow = tid >> 2, acol = (tid & 3) * 8;
    int brow = tid >> 4, bcol = (tid & 15) * 4;

    float acc[2][4][4];
#pragma unroll
    for (int mt = 0; mt < 2; mt++)
#pragma unroll
        for (int nt = 0; nt < 4; nt++)
#pragma unroll
            for (int i = 0; i < 4; i++) acc[mt][nt][i] = 0.f;

    uint4 aReg[2];
    float4 bReg[2];
#pragma unroll
    for (int i = 0; i < 2; i++)
        aReg[i] = *(const uint4*)&A[(size_t)(row0 + arow + 64 * i) * K + acol];
#pragma unroll
    for (int i = 0; i < 2; i++)
        bReg[i] = *(const float4*)&Bw[(size_t)(brow + 16 * i) * N + col0 + bcol];

#pragma unroll
    for (int i = 0; i < 2; i++) {
        uint32_t* p = (uint32_t*)&AsH[(arow + 64 * i) * 40 + acol];
        p[0] = aReg[i].x; p[1] = aReg[i].y; p[2] = aReg[i].z; p[3] = aReg[i].w;
    }
#pragma unroll
    for (int i = 0; i < 2; i++) {
        int kk = brow + 16 * i;
        BsH[(bcol + 0) * 40 + kk] = __float2bfloat16(bReg[i].x);
        BsH[(bcol + 1) * 40 + kk] = __float2bfloat16(bReg[i].y);
        BsH[(bcol + 2) * 40 + kk] = __float2bfloat16(bReg[i].z);
        BsH[(bcol + 3) * 40 + kk] = __float2bfloat16(bReg[i].w);
    }

    for (int k0 = 0;;) {
        __syncthreads();
        bool more = (k0 + 32 < K);
        if (more) {
#pragma unroll
            for (int i = 0; i < 2; i++)
                aReg[i] = *(const uint4*)&A[(size_t)(row0 + arow + 64 * i) * K + k0 + 32 + acol];
#pragma unroll
            for (int i = 0; i < 2; i++)
                bReg[i] = *(const float4*)&Bw[(size_t)(k0 + 32 + brow + 16 * i) * N + col0 + bcol];
        }
#pragma unroll
        for (int kk = 0; kk < 32; kk += 16) {
            uint32_t afr[2][4];
#pragma unroll
            for (int mt = 0; mt < 2; mt++) {
                int m = warpM * 32 + mt * 16 + gid;
                afr[mt][0] = *(const uint32_t*)&AsH[m * 40 + kk + 2 * tig];
                afr[mt][1] = *(const uint32_t*)&AsH[(m + 8) * 40 + kk + 2 * tig];
                afr[mt][2] = *(const uint32_t*)&AsH[m * 40 + kk + 8 + 2 * tig];
                afr[mt][3] = *(const uint32_t*)&AsH[(m + 8) * 40 + kk + 8 + 2 * tig];
            }
            uint32_t bfr[4][2];
#pragma unroll
            for (int nt = 0; nt < 4; nt++) {
                int n = warpN * 32 + nt * 8 + gid;
                bfr[nt][0] = *(const uint32_t*)&BsH[n * 40 + kk + 2 * tig];
                bfr[nt][1] = *(const uint32_t*)&BsH[n * 40 + kk + 8 + 2 * tig];
            }
#pragma unroll
            for (int mt = 0; mt < 2; mt++)
#pragma unroll
                for (int nt = 0; nt < 4; nt++)
                    mma_bf16(acc[mt][nt], afr[mt], bfr[nt]);
        }
        k0 += 32;
        if (!more) break;
        __syncthreads();
#pragma unroll
        for (int i = 0; i < 2; i++) {
            uint32_t* p = (uint32_t*)&AsH[(arow + 64 * i) * 40 + acol];
            p[0] = aReg[i].x; p[1] = aReg[i].y; p[2] = aReg[i].z; p[3] = aReg[i].w;
        }
#pragma unroll
        for (int i = 0; i < 2; i++) {
            int kk = brow + 16 * i;
            BsH[(bcol + 0) * 40 + kk] = __float2bfloat16(bReg[i].x);
            BsH[(bcol + 1) * 40 + kk] = __float2bfloat16(bReg[i].y);
            BsH[(bcol + 2) * 40 + kk] = __float2bfloat16(bReg[i].z);
            BsH[(bcol + 3) * 40 + kk] = __float2bfloat16(bReg[i].w);
        }
    }

    const float QK_SCALE = 0.17677669529663687f;   // 32^-0.5
#pragma unroll
    for (int mt = 0; mt < 2; mt++) {
        int rbase = row0 + warpM * 32 + mt * 16 + gid;
#pragma unroll
        for (int half = 0; half < 2; half++) {
            int row = rbase + half * 8;
            int obase1 = 0;
            if (mode == 1) obase1 = winrow_to_orig(row) * C_DIM;
#pragma unroll
            for (int nt = 0; nt < 4; nt++) {
                int col = col0 + warpN * 32 + nt * 8 + 2 * tig;
                float v0 = acc[mt][nt][half * 2 + 0] + bias[col];
                float v1 = acc[mt][nt][half * 2 + 1] + bias[col + 1];
                if (mode == 0) {
                    int wi = row >> 6, n = row & 63;
                    int which = col / 192;
                    int rem = col - which * 192;
                    int head = rem >> 5, hdi = rem & 31;
                    float sc = (which == 0) ? QK_SCALE : 1.0f;
                    uint32_t* p = (uint32_t*)&g_qkv[(((which * NWIN + wi) * HEADS + head) << 11) + (n << 5) + hdi];
                    *p = packbf2(v0 * sc, v1 * sc);
                } else if (mode == 1) {
                    float* p = &g_xo[obase1 + col];
                    const float* r = &xres[obase1 + col];
                    *(float2*)p = make_float2(v0 + r[0], v1 + r[1]);
                } else if (mode == 2) {
                    uint32_t* p = (uint32_t*)&g_h1[(size_t)row * HID + col];
                    *p = packbf2(gelu_exact(v0), gelu_exact(v1));
                } else {
                    size_t o = (size_t)row * C_DIM + col;
                    *(float2*)&dout[o] = make_float2(v0 + g_xo[o], v1 + g_xo[o + 1]);
                }
            }
        }
    }
}

// ---------------- attention: tensor-core, 1 block per (window, head) -------
// 128 threads = 4 warps; warp w owns rows [16w, 16w+16).
__global__ __launch_bounds__(128) void attn_kernel(const float* __restrict__ bias_table) {
    __shared__ __nv_bfloat16 sQ[64 * 40];    // [tok][hd], stride 40
    __shared__ __nv_bfloat16 sK[64 * 40];    // [tok][hd], stride 40
    __shared__ __nv_bfloat16 sVT[32 * 72];   // [hd][tok], stride 72
    __shared__ float sBias[343];
    __shared__ unsigned char sReg[64];

    int wi = blockIdx.x / HEADS, head = blockIdx.x % HEADS;
    int tid = threadIdx.x;
    int warp = tid >> 5, lane = tid & 31;
    int g = lane >> 2, q4 = lane & 3;

    const __nv_bfloat16* Qg = g_qkv + (((0 * NWIN + wi) * HEADS + head) << 11);
    const __nv_bfloat16* Kg = g_qkv + (((1 * NWIN + wi) * HEADS + head) << 11);
    const __nv_bfloat16* Vg = g_qkv + (((2 * NWIN + wi) * HEADS + head) << 11);

    // load Q, K (uint4 = 8 bf16)
#pragma unroll
    for (int i = tid; i < 256; i += 128) {
        int r = i >> 2, c = (i & 3) * 8;
        *(uint4*)&sQ[r * 40 + c] = *(const uint4*)&Qg[r * 32 + c];
        *(uint4*)&sK[r * 40 + c] = *(const uint4*)&Kg[r * 32 + c];
    }
    // V transposed: [hd][tok]
#pragma unroll
    for (int i = tid; i < 2048; i += 128) {
        int tk = i >> 5, d = i & 31;
        sVT[d * 72 + tk] = Vg[i];
    }
    if (tid < 64) {
        int Hb = (wi >> 6) & 7, Wb = (wi >> 3) & 7, Db = wi & 7;
        int ih = tid >> 4, iw = (tid >> 2) & 3, id = tid & 3;
        int rh = (Hb == 7) ? (ih >= 2 ? 2 : 1) : 0;
        int rw = (Wb == 7) ? (iw >= 2 ? 2 : 1) : 0;
        int rd = (Db == 7) ? (id >= 2 ? 2 : 1) : 0;
        sReg[tid] = (unsigned char)(rh * 9 + rw * 3 + rd);
    }
    for (int i = tid; i < 343; i += 128) sBias[i] = bias_table[i * HEADS + head];
    __syncthreads();

    int m0 = warp * 16;
    // A fragments of Q (q pre-scaled by hd^-0.5 at QKV epilogue)
    uint32_t af[2][4];
#pragma unroll
    for (int kt = 0; kt < 2; kt++) {
        int kk = kt * 16;
        af[kt][0] = *(const uint32_t*)&sQ[(m0 + g) * 40 + kk + 2 * q4];
        af[kt][1] = *(const uint32_t*)&sQ[(m0 + g + 8) * 40 + kk + 2 * q4];
        af[kt][2] = *(const uint32_t*)&sQ[(m0 + g) * 40 + kk + 8 + 2 * q4];
        af[kt][3] = *(const uint32_t*)&sQ[(m0 + g + 8) * 40 + kk + 8 + 2 * q4];
    }
    float c[8][4];
#pragma unroll
    for (int nt = 0; nt < 8; nt++)
#pragma unroll
        for (int i = 0; i < 4; i++) c[nt][i] = 0.f;
#pragma unroll
    for (int nt = 0; nt < 8; nt++) {
#pragma unroll
        for (int kt = 0; kt < 2; kt++) {
            uint32_t bf[2];
            bf[0] = *(const uint32_t*)&sK[(nt * 8 + g) * 40 + kt * 16 + 2 * q4];
            bf[1] = *(const uint32_t*)&sK[(nt * 8 + g) * 40 + kt * 16 + 8 + 2 * q4];
            mma_bf16(c[nt], af[kt], bf);
        }
    }

    // bias + mask in fragments
    int i0 = m0 + g, i1 = i0 + 8;
    int base0 = (i0 >> 4) * 49 + ((i0 >> 2) & 3) * 7 + (i0 & 3);
    int base1 = (i1 >> 4) * 49 + ((i1 >> 2) & 3) * 7 + (i1 & 3);
    int r0 = sReg[i0], r1 = sReg[i1];
#pragma unroll
    for (int nt = 0; nt < 8; nt++) {
#pragma unroll
        for (int e = 0; e < 2; e++) {
            int j = nt * 8 + 2 * q4 + e;
            int jb = (j >> 4) * 49 + ((j >> 2) & 3) * 7 + (j & 3);
            int rj = sReg[j];
            c[nt][e]     += sBias[base0 - jb + 171] + ((r0 == rj) ? 0.f : -100.f);
            c[nt][2 + e] += sBias[base1 - jb + 171] + ((r1 == rj) ? 0.f : -100.f);
        }
    }

    // softmax (rows i0 and i1 live in this lane quad)
    float mx0 = -1e30f, mx1 = -1e30f;
#pragma unroll
    for (int nt = 0; nt < 8; nt++) {
        mx0 = fmaxf(mx0, fmaxf(c[nt][0], c[nt][1]));
        mx1 = fmaxf(mx1, fmaxf(c[nt][2], c[nt][3]));
    }
    mx0 = fmaxf(mx0, __shfl_xor_sync(0xffffffffu, mx0, 1));
    mx0 = fmaxf(mx0, __shfl_xor_sync(0xffffffffu, mx0, 2));
    mx1 = fmaxf(mx1, __shfl_xor_sync(0xffffffffu, mx1, 1));
    mx1 = fmaxf(mx1, __shfl_xor_sync(0xffffffffu, mx1, 2));
    float s0 = 0.f, s1 = 0.f;
#pragma unroll
    for (int nt = 0; nt < 8; nt++) {
        c[nt][0] = __expf(c[nt][0] - mx0); s0 += c[nt][0];
        c[nt][1] = __expf(c[nt][1] - mx0); s0 += c[nt][1];
        c[nt][2] = __expf(c[nt][2] - mx1); s1 += c[nt][2];
        c[nt][3] = __expf(c[nt][3] - mx1); s1 += c[nt][3];
    }
    s0 += __shfl_xor_sync(0xffffffffu, s0, 1);
    s0 += __shfl_xor_sync(0xffffffffu, s0, 2);
    s1 += __shfl_xor_sync(0xffffffffu, s1, 1);
    s1 += __shfl_xor_sync(0xffffffffu, s1, 2);
    float inv0 = 1.0f / s0, inv1 = 1.0f / s1;
#pragma unroll
    for (int nt = 0; nt < 8; nt++) {
        c[nt][0] *= inv0; c[nt][1] *= inv0;
        c[nt][2] *= inv1; c[nt][3] *= inv1;
    }

    // repack P into bf16 A-fragments (QK C layout == PV A layout)
    uint32_t pa[4][4];
#pragma unroll
    for (int kt = 0; kt < 4; kt++) {
        pa[kt][0] = packbf2(c[2 * kt][0], c[2 * kt][1]);
        pa[kt][1] = packbf2(c[2 * kt][2], c[2 * kt][3]);
        pa[kt][2] = packbf2(c[2 * kt + 1][0], c[2 * kt + 1][1]);
        pa[kt][3] = packbf2(c[2 * kt + 1][2], c[2 * kt + 1][3]);
    }
    float d[4][4];
#pragma unroll
    for (int nt = 0; nt < 4; nt++)
#pragma unroll
        for (int i = 0; i < 4; i++) d[nt][i] = 0.f;
#pragma unroll
    for (int nt = 0; nt < 4; nt++) {
#pragma unroll
        for (int kt = 0; kt < 4; kt++) {
            uint32_t bf[2];
            bf[0] = *(const uint32_t*)&sVT[(nt * 8 + g) * 72 + kt * 16 + 2 * q4];
            bf[1] = *(const uint32_t*)&sVT[(nt * 8 + g) * 72 + kt * 16 + 8 + 2 * q4];
            mma_bf16(d[nt], pa[kt], bf);
        }
    }

    // store to g_attnout (window layout, bf16)
    size_t ob0 = (size_t)(wi * 64 + i0) * C_DIM + head * 32;
    size_t ob1 = (size_t)(wi * 64 + i1) * C_DIM + head * 32;
#pragma unroll
    for (int nt = 0; nt < 4; nt++) {
        int col = nt * 8 + 2 * q4;
        *(uint32_t*)&g_attnout[ob0 + col] = packbf2(d[nt][0], d[nt][1]);
        *(uint32_t*)&g_attnout[ob1 + col] = packbf2(d[nt][2], d[nt][3]);
    }
}

extern "C" void kernel_launch(void* const* d_in, const int* in_sizes, int n_in,
                              void* d_out, int out_size) {
    const float* x          = (const float*)d_in[0];
    const float* g1         = (const float*)d_in[1];
    const float* b1         = (const float*)d_in[2];
    const float* wqkv       = (const float*)d_in[3];
    const float* bqkv       = (const float*)d_in[4];
    const float* wo         = (const float*)d_in[5];
    const float* bo         = (const float*)d_in[6];
    const float* bias_table = (const float*)d_in[7];
    const float* g2         = (const float*)d_in[8];
    const float* b2         = (const float*)d_in[9];
    const float* w1         = (const float*)d_in[10];
    const float* bm1        = (const float*)d_in[11];
    const float* w2         = (const float*)d_in[12];
    const float* bm2        = (const float*)d_in[13];
    float* out              = (float*)d_out;

    // 1. LN1 + shift + window partition (bf16 out)
    ln_kernel<<<M_TOT / 8, 256>>>(x, g1, b1, 0);
    // 2. QKV projection (bf16 mma; bf16 qkv out, q pre-scaled)
    gemm_bf16<<<dim3(576 / 64, M_TOT / 128), 256>>>(wqkv, bqkv, nullptr, nullptr, C_DIM, 576, 0);
    // 3. windowed attention (tensor-core)
    attn_kernel<<<NWIN * HEADS, 128>>>(bias_table);
    // 4. output projection + reverse shift + residual -> xo (fp32)
    gemm_bf16<<<dim3(192 / 64, M_TOT / 128), 256>>>(wo, bo, x, nullptr, C_DIM, C_DIM, 1);
    // 5. LN2 (bf16 out)
    ln_kernel<<<M_TOT / 8, 256>>>(nullptr, g2, b2, 1);
    // 6. fc1 + gelu (bf16 out)
    gemm_bf16<<<dim3(768 / 64, M_TOT / 128), 256>>>(w1, bm1, nullptr, nullptr, C_DIM, HID, 2);
    // 7. fc2 + residual -> out (fp32)
    gemm_bf16<<<dim3(192 / 64, M_TOT / 128), 256>>>(w2, bm2, nullptr, out, HID, C_DIM, 3);
}

// round 11
// speedup vs baseline: 4.2691x; 1.5137x over previous
#include <cuda_runtime.h>
#include <cuda_bf16.h>
#include <math.h>
#include <stdint.h>

// ---------------- problem constants ----------------
#define BATCH 2
#define GRID_DIM 32
#define C_DIM 192
#define HEADS 6
#define HD 32
#define NTOK 64
#define NWIN 1024
#define M_TOT (NWIN * NTOK)
#define HID 768
#define SHIFT_AMT 2

// ---------------- scratch (device globals; no allocs) ----------------
__device__ __nv_bfloat16 g_xw[M_TOT * C_DIM];
__device__ __nv_bfloat16 g_qkv[3 * NWIN * HEADS * NTOK * HD]; // q pre-scaled
__device__ __nv_bfloat16 g_attnout[M_TOT * C_DIM];
__device__ float         g_xo[M_TOT * C_DIM];
__device__ __nv_bfloat16 g_xn2[M_TOT * C_DIM];
__device__ __nv_bfloat16 g_h1[M_TOT * HID];
// transposed bf16 weights [N][K]
__device__ __nv_bfloat16 g_wqkvT[576 * 192];
__device__ __nv_bfloat16 g_woT[192 * 192];
__device__ __nv_bfloat16 g_w1T[768 * 192];
__device__ __nv_bfloat16 g_w2T[192 * 768];

// ---------------- helpers ----------------
__device__ __forceinline__ float gelu_exact(float v) {
    return 0.5f * v * (1.0f + erff(v * 0.70710678118654752f));
}
__device__ __forceinline__ void mma_bf16(float (&c)[4], const uint32_t (&a)[4],
                                         const uint32_t (&b)[2]) {
    asm volatile(
        "mma.sync.aligned.m16n8k16.row.col.f32.bf16.bf16.f32 "
        "{%0,%1,%2,%3}, {%4,%5,%6,%7}, {%8,%9}, {%0,%1,%2,%3};"
        : "+f"(c[0]), "+f"(c[1]), "+f"(c[2]), "+f"(c[3])
        : "r"(a[0]), "r"(a[1]), "r"(a[2]), "r"(a[3]), "r"(b[0]), "r"(b[1]));
}
__device__ __forceinline__ uint32_t packbf2(float a, float b) {
    __nv_bfloat162 t = __floats2bfloat162_rn(a, b);
    return *(uint32_t*)&t;
}
__device__ __forceinline__ uint32_t smem_u32(const void* p) {
    return (uint32_t)__cvta_generic_to_shared(p);
}
#define CP16(dst, src) \
    asm volatile("cp.async.cg.shared.global [%0], [%1], 16;" :: "r"(dst), "l"(src))
#define CP_COMMIT() asm volatile("cp.async.commit_group;")
#define CP_WAIT1()  asm volatile("cp.async.wait_group 1;")

__device__ __forceinline__ int winrow_to_orig(int t) {
    int wi = t >> 6, n = t & 63;
    int b  = wi >> 9;
    int Hb = (wi >> 6) & 7, Wb = (wi >> 3) & 7, Db = wi & 7;
    int i = n >> 4, j = (n >> 2) & 3, k = n & 3;
    int h = ((Hb << 2) + i + SHIFT_AMT) & 31;
    int w = ((Wb << 2) + j + SHIFT_AMT) & 31;
    int d = ((Db << 2) + k + SHIFT_AMT) & 31;
    return (((b * 32 + h) * 32 + w) * 32 + d);
}

// ---------------- weight prep: fp32 [K][N] -> bf16 [N][K] ----------------
__global__ __launch_bounds__(256) void prep_w(const float* __restrict__ src,
                                              __nv_bfloat16* __restrict__ dst,
                                              int K, int N) {
    int i = blockIdx.x * 256 + threadIdx.x;
    if (i >= K * N) return;
    int n = i / K, k = i - n * K;
    dst[i] = __float2bfloat16(src[k * N + n]);
}

// ---------------- LN kernels (warp per token), bf16 output ----------------
__global__ __launch_bounds__(256) void ln_kernel(const float* __restrict__ xin,
                                                 const float* __restrict__ gma,
                                                 const float* __restrict__ bta,
                                                 int mode) {
    int warp = threadIdx.x >> 5, lane = threadIdx.x & 31;
    int t = blockIdx.x * 8 + warp;
    const float* src;
    __nv_bfloat16* dst;
    if (mode == 0) {
        src = xin + (size_t)winrow_to_orig(t) * C_DIM;
        dst = g_xw + (size_t)t * C_DIM;
    } else {
        src = g_xo + (size_t)t * C_DIM;
        dst = g_xn2 + (size_t)t * C_DIM;
    }
    float v[6];
    float s = 0.f;
#pragma unroll
    for (int k = 0; k < 6; k++) { v[k] = src[lane + 32 * k]; s += v[k]; }
#pragma unroll
    for (int o = 16; o > 0; o >>= 1) s += __shfl_xor_sync(0xffffffffu, s, o);
    float mean = s * (1.0f / C_DIM);
    float q = 0.f;
#pragma unroll
    for (int k = 0; k < 6; k++) { float d = v[k] - mean; q += d * d; }
#pragma unroll
    for (int o = 16; o > 0; o >>= 1) q += __shfl_xor_sync(0xffffffffu, q, o);
    float rstd = rsqrtf(q * (1.0f / C_DIM) + 1e-5f);
#pragma unroll
    for (int k = 0; k < 6; k++) {
        int c = lane + 32 * k;
        dst[c] = __float2bfloat16((v[k] - mean) * rstd * gma[c] + bta[c]);
    }
}

// ---------------- bf16 GEMM, cp.async 3-stage pipeline ----------------
// Block tile 128x64, k-step 32, 256 threads = 8 warps (4x2), warp tile 32x32.
// A bf16 [M][K]; B bf16 transposed [N][K].
__global__ __launch_bounds__(256) void gemm_bf16(const __nv_bfloat16* __restrict__ BwT,
                                                 const float* __restrict__ bias,
                                                 const float* __restrict__ xres,
                                                 float* __restrict__ dout,
                                                 int K, int N, int mode) {
    const __nv_bfloat16* A = (mode == 0) ? g_xw
                           : (mode == 1) ? g_attnout
                           : (mode == 2) ? g_xn2
                                         : g_h1;
    __shared__ __nv_bfloat16 AsH[3][128 * 40];   // [m][k], stride 40
    __shared__ __nv_bfloat16 BsH[3][64 * 40];    // [n][k], stride 40

    int tid = threadIdx.x;
    int warp = tid >> 5, lane = tid & 31;
    int gid = lane >> 2, tig = lane & 3;
    int warpM = warp & 3, warpN = warp >> 2;
    int row0 = blockIdx.y * 128, col0 = blockIdx.x * 64;

    // cp.async coordinates
    int aRow = tid >> 1, aCol = (tid & 1) * 16;     // 2 chunks of 8 bf16 each
    int bRow = tid >> 2, bCol = (tid & 3) * 8;      // 1 chunk
    const __nv_bfloat16* aSrc = A + (size_t)(row0 + aRow) * K + aCol;
    const __nv_bfloat16* bSrc = BwT + (size_t)(col0 + bRow) * K + bCol;

    int NK = K >> 5;

    float acc[2][4][4];
#pragma unroll
    for (int mt = 0; mt < 2; mt++)
#pragma unroll
        for (int nt = 0; nt < 4; nt++)
#pragma unroll
            for (int i = 0; i < 4; i++) acc[mt][nt][i] = 0.f;

    // prologue: stages 0,1
#pragma unroll
    for (int s = 0; s < 2; s++) {
        if (s < NK) {
            uint32_t ad = smem_u32(&AsH[s][aRow * 40 + aCol]);
            CP16(ad, aSrc + s * 32);
            CP16(ad + 16, aSrc + s * 32 + 8);
            uint32_t bd = smem_u32(&BsH[s][bRow * 40 + bCol]);
            CP16(bd, bSrc + s * 32);
        }
        CP_COMMIT();
    }

    for (int ki = 0; ki < NK; ki++) {
        CP_WAIT1();
        __syncthreads();
        int kn = ki + 2;
        if (kn < NK) {
            int st = kn % 3;
            uint32_t ad = smem_u32(&AsH[st][aRow * 40 + aCol]);
            CP16(ad, aSrc + kn * 32);
            CP16(ad + 16, aSrc + kn * 32 + 8);
            uint32_t bd = smem_u32(&BsH[st][bRow * 40 + bCol]);
            CP16(bd, bSrc + kn * 32);
        }
        CP_COMMIT();

        int s = ki % 3;
        const __nv_bfloat16* As = AsH[s];
        const __nv_bfloat16* Bs = BsH[s];
#pragma unroll
        for (int kk = 0; kk < 32; kk += 16) {
            uint32_t afr[2][4];
#pragma unroll
            for (int mt = 0; mt < 2; mt++) {
                int m = warpM * 32 + mt * 16 + gid;
                afr[mt][0] = *(const uint32_t*)&As[m * 40 + kk + 2 * tig];
                afr[mt][1] = *(const uint32_t*)&As[(m + 8) * 40 + kk + 2 * tig];
                afr[mt][2] = *(const uint32_t*)&As[m * 40 + kk + 8 + 2 * tig];
                afr[mt][3] = *(const uint32_t*)&As[(m + 8) * 40 + kk + 8 + 2 * tig];
            }
            uint32_t bfr[4][2];
#pragma unroll
            for (int nt = 0; nt < 4; nt++) {
                int n = warpN * 32 + nt * 8 + gid;
                bfr[nt][0] = *(const uint32_t*)&Bs[n * 40 + kk + 2 * tig];
                bfr[nt][1] = *(const uint32_t*)&Bs[n * 40 + kk + 8 + 2 * tig];
            }
#pragma unroll
            for (int mt = 0; mt < 2; mt++)
#pragma unroll
                for (int nt = 0; nt < 4; nt++)
                    mma_bf16(acc[mt][nt], afr[mt], bfr[nt]);
        }
    }

    const float QK_SCALE = 0.17677669529663687f;
#pragma unroll
    for (int mt = 0; mt < 2; mt++) {
        int rbase = row0 + warpM * 32 + mt * 16 + gid;
#pragma unroll
        for (int half = 0; half < 2; half++) {
            int row = rbase + half * 8;
            int obase1 = 0;
            if (mode == 1) obase1 = winrow_to_orig(row) * C_DIM;
#pragma unroll
            for (int nt = 0; nt < 4; nt++) {
                int col = col0 + warpN * 32 + nt * 8 + 2 * tig;
                float v0 = acc[mt][nt][half * 2 + 0] + bias[col];
                float v1 = acc[mt][nt][half * 2 + 1] + bias[col + 1];
                if (mode == 0) {
                    int wi = row >> 6, n = row & 63;
                    int which = col / 192;
                    int rem = col - which * 192;
                    int head = rem >> 5, hdi = rem & 31;
                    float sc = (which == 0) ? QK_SCALE : 1.0f;
                    uint32_t* p = (uint32_t*)&g_qkv[(((which * NWIN + wi) * HEADS + head) << 11) + (n << 5) + hdi];
                    *p = packbf2(v0 * sc, v1 * sc);
                } else if (mode == 1) {
                    float* p = &g_xo[obase1 + col];
                    const float* r = &xres[obase1 + col];
                    *(float2*)p = make_float2(v0 + r[0], v1 + r[1]);
                } else if (mode == 2) {
                    uint32_t* p = (uint32_t*)&g_h1[(size_t)row * HID + col];
                    *p = packbf2(gelu_exact(v0), gelu_exact(v1));
                } else {
                    size_t o = (size_t)row * C_DIM + col;
                    *(float2*)&dout[o] = make_float2(v0 + g_xo[o], v1 + g_xo[o + 1]);
                }
            }
        }
    }
}

// ---------------- attention: tensor-core, 1 block per (window, head) -------
__global__ __launch_bounds__(128) void attn_kernel(const float* __restrict__ bias_table) {
    __shared__ __nv_bfloat16 sQ[64 * 40];
    __shared__ __nv_bfloat16 sK[64 * 40];
    __shared__ __nv_bfloat16 sVT[32 * 72];
    __shared__ float sBias[343];
    __shared__ unsigned char sReg[64];

    int wi = blockIdx.x / HEADS, head = blockIdx.x % HEADS;
    int tid = threadIdx.x;
    int warp = tid >> 5, lane = tid & 31;
    int g = lane >> 2, q4 = lane & 3;

    const __nv_bfloat16* Qg = g_qkv + (((0 * NWIN + wi) * HEADS + head) << 11);
    const __nv_bfloat16* Kg = g_qkv + (((1 * NWIN + wi) * HEADS + head) << 11);
    const __nv_bfloat16* Vg = g_qkv + (((2 * NWIN + wi) * HEADS + head) << 11);

#pragma unroll
    for (int i = tid; i < 256; i += 128) {
        int r = i >> 2, c = (i & 3) * 8;
        *(uint4*)&sQ[r * 40 + c] = *(const uint4*)&Qg[r * 32 + c];
        *(uint4*)&sK[r * 40 + c] = *(const uint4*)&Kg[r * 32 + c];
        // V: vector load, transpose into sVT
        uint4 v = *(const uint4*)&Vg[r * 32 + c];
        __nv_bfloat16 tmp[8];
        *(uint4*)tmp = v;
#pragma unroll
        for (int j = 0; j < 8; j++) sVT[(c + j) * 72 + r] = tmp[j];
    }
    if (tid < 64) {
        int Hb = (wi >> 6) & 7, Wb = (wi >> 3) & 7, Db = wi & 7;
        int ih = tid >> 4, iw = (tid >> 2) & 3, id = tid & 3;
        int rh = (Hb == 7) ? (ih >= 2 ? 2 : 1) : 0;
        int rw = (Wb == 7) ? (iw >= 2 ? 2 : 1) : 0;
        int rd = (Db == 7) ? (id >= 2 ? 2 : 1) : 0;
        sReg[tid] = (unsigned char)(rh * 9 + rw * 3 + rd);
    }
    for (int i = tid; i < 343; i += 128) sBias[i] = bias_table[i * HEADS + head];
    __syncthreads();

    int m0 = warp * 16;
    uint32_t af[2][4];
#pragma unroll
    for (int kt = 0; kt < 2; kt++) {
        int kk = kt * 16;
        af[kt][0] = *(const uint32_t*)&sQ[(m0 + g) * 40 + kk + 2 * q4];
        af[kt][1] = *(const uint32_t*)&sQ[(m0 + g + 8) * 40 + kk + 2 * q4];
        af[kt][2] = *(const uint32_t*)&sQ[(m0 + g) * 40 + kk + 8 + 2 * q4];
        af[kt][3] = *(const uint32_t*)&sQ[(m0 + g + 8) * 40 + kk + 8 + 2 * q4];
    }
    float c[8][4];
#pragma unroll
    for (int nt = 0; nt < 8; nt++)
#pragma unroll
        for (int i = 0; i < 4; i++) c[nt][i] = 0.f;
#pragma unroll
    for (int nt = 0; nt < 8; nt++) {
#pragma unroll
        for (int kt = 0; kt < 2; kt++) {
            uint32_t bf[2];
            bf[0] = *(const uint32_t*)&sK[(nt * 8 + g) * 40 + kt * 16 + 2 * q4];
            bf[1] = *(const uint32_t*)&sK[(nt * 8 + g) * 40 + kt * 16 + 8 + 2 * q4];
            mma_bf16(c[nt], af[kt], bf);
        }
    }

    int i0 = m0 + g, i1 = i0 + 8;
    int base0 = (i0 >> 4) * 49 + ((i0 >> 2) & 3) * 7 + (i0 & 3);
    int base1 = (i1 >> 4) * 49 + ((i1 >> 2) & 3) * 7 + (i1 & 3);
    int r0 = sReg[i0], r1 = sReg[i1];
#pragma unroll
    for (int nt = 0; nt < 8; nt++) {
#pragma unroll
        for (int e = 0; e < 2; e++) {
            int j = nt * 8 + 2 * q4 + e;
            int jb = (j >> 4) * 49 + ((j >> 2) & 3) * 7 + (j & 3);
            int rj = sReg[j];
            c[nt][e]     += sBias[base0 - jb + 171] + ((r0 == rj) ? 0.f : -100.f);
            c[nt][2 + e] += sBias[base1 - jb + 171] + ((r1 == rj) ? 0.f : -100.f);
        }
    }

    float mx0 = -1e30f, mx1 = -1e30f;
#pragma unroll
    for (int nt = 0; nt < 8; nt++) {
        mx0 = fmaxf(mx0, fmaxf(c[nt][0], c[nt][1]));
        mx1 = fmaxf(mx1, fmaxf(c[nt][2], c[nt][3]));
    }
    mx0 = fmaxf(mx0, __shfl_xor_sync(0xffffffffu, mx0, 1));
    mx0 = fmaxf(mx0, __shfl_xor_sync(0xffffffffu, mx0, 2));
    mx1 = fmaxf(mx1, __shfl_xor_sync(0xffffffffu, mx1, 1));
    mx1 = fmaxf(mx1, __shfl_xor_sync(0xffffffffu, mx1, 2));
    float s0 = 0.f, s1 = 0.f;
#pragma unroll
    for (int nt = 0; nt < 8; nt++) {
        c[nt][0] = __expf(c[nt][0] - mx0); s0 += c[nt][0];
        c[nt][1] = __expf(c[nt][1] - mx0); s0 += c[nt][1];
        c[nt][2] = __expf(c[nt][2] - mx1); s1 += c[nt][2];
        c[nt][3] = __expf(c[nt][3] - mx1); s1 += c[nt][3];
    }
    s0 += __shfl_xor_sync(0xffffffffu, s0, 1);
    s0 += __shfl_xor_sync(0xffffffffu, s0, 2);
    s1 += __shfl_xor_sync(0xffffffffu, s1, 1);
    s1 += __shfl_xor_sync(0xffffffffu, s1, 2);
    float inv0 = 1.0f / s0, inv1 = 1.0f / s1;
#pragma unroll
    for (int nt = 0; nt < 8; nt++) {
        c[nt][0] *= inv0; c[nt][1] *= inv0;
        c[nt][2] *= inv1; c[nt][3] *= inv1;
    }

    uint32_t pa[4][4];
#pragma unroll
    for (int kt = 0; kt < 4; kt++) {
        pa[kt][0] = packbf2(c[2 * kt][0], c[2 * kt][1]);
        pa[kt][1] = packbf2(c[2 * kt][2], c[2 * kt][3]);
        pa[kt][2] = packbf2(c[2 * kt + 1][0], c[2 * kt + 1][1]);
        pa[kt][3] = packbf2(c[2 * kt + 1][2], c[2 * kt + 1][3]);
    }
    float d[4][4];
#pragma unroll
    for (int nt = 0; nt < 4; nt++)
#pragma unroll
        for (int i = 0; i < 4; i++) d[nt][i] = 0.f;
#pragma unroll
    for (int nt = 0; nt < 4; nt++) {
#pragma unroll
        for (int kt = 0; kt < 4; kt++) {
            uint32_t bf[2];
            bf[0] = *(const uint32_t*)&sVT[(nt * 8 + g) * 72 + kt * 16 + 2 * q4];
            bf[1] = *(const uint32_t*)&sVT[(nt * 8 + g) * 72 + kt * 16 + 8 + 2 * q4];
            mma_bf16(d[nt], pa[kt], bf);
        }
    }

    size_t ob0 = (size_t)(wi * 64 + i0) * C_DIM + head * 32;
    size_t ob1 = (size_t)(wi * 64 + i1) * C_DIM + head * 32;
#pragma unroll
    for (int nt = 0; nt < 4; nt++) {
        int col = nt * 8 + 2 * q4;
        *(uint32_t*)&g_attnout[ob0 + col] = packbf2(d[nt][0], d[nt][1]);
        *(uint32_t*)&g_attnout[ob1 + col] = packbf2(d[nt][2], d[nt][3]);
    }
}

extern "C" void kernel_launch(void* const* d_in, const int* in_sizes, int n_in,
                              void* d_out, int out_size) {
    const float* x          = (const float*)d_in[0];
    const float* g1         = (const float*)d_in[1];
    const float* b1         = (const float*)d_in[2];
    const float* wqkv       = (const float*)d_in[3];
    const float* bqkv       = (const float*)d_in[4];
    const float* wo         = (const float*)d_in[5];
    const float* bo         = (const float*)d_in[6];
    const float* bias_table = (const float*)d_in[7];
    const float* g2         = (const float*)d_in[8];
    const float* b2         = (const float*)d_in[9];
    const float* w1         = (const float*)d_in[10];
    const float* bm1        = (const float*)d_in[11];
    const float* w2         = (const float*)d_in[12];
    const float* bm2        = (const float*)d_in[13];
    float* out              = (float*)d_out;

    __nv_bfloat16 *wqkvT, *woT, *w1T, *w2T;
    cudaGetSymbolAddress((void**)&wqkvT, g_wqkvT);
    cudaGetSymbolAddress((void**)&woT, g_woT);
    cudaGetSymbolAddress((void**)&w1T, g_w1T);
    cudaGetSymbolAddress((void**)&w2T, g_w2T);

    // 0. weight prep (bf16 transposed)
    prep_w<<<(576 * 192 + 255) / 256, 256>>>(wqkv, wqkvT, 192, 576);
    prep_w<<<(192 * 192 + 255) / 256, 256>>>(wo, woT, 192, 192);
    prep_w<<<(192 * 768 + 255) / 256, 256>>>(w1, w1T, 192, 768);
    prep_w<<<(768 * 192 + 255) / 256, 256>>>(w2, w2T, 768, 192);

    // 1. LN1 + shift + window partition
    ln_kernel<<<M_TOT / 8, 256>>>(x, g1, b1, 0);
    // 2. QKV projection
    gemm_bf16<<<dim3(576 / 64, M_TOT / 128), 256>>>(wqkvT, bqkv, nullptr, nullptr, C_DIM, 576, 0);
    // 3. windowed attention
    attn_kernel<<<NWIN * HEADS, 128>>>(bias_table);
    // 4. output projection + reverse shift + residual
    gemm_bf16<<<dim3(192 / 64, M_TOT / 128), 256>>>(woT, bo, x, nullptr, C_DIM, C_DIM, 1);
    // 5. LN2
    ln_kernel<<<M_TOT / 8, 256>>>(nullptr, g2, b2, 1);
    // 6. fc1 + gelu
    gemm_bf16<<<dim3(768 / 64, M_TOT / 128), 256>>>(w1T, bm1, nullptr, nullptr, C_DIM, HID, 2);
    // 7. fc2 + residual -> out
    gemm_bf16<<<dim3(192 / 64, M_TOT / 128), 256>>>(w2T, bm2, nullptr, out, HID, C_DIM, 3);
}

// round 12
// speedup vs baseline: 4.4837x; 1.0503x over previous
#include <cuda_runtime.h>
#include <cuda_bf16.h>
#include <math.h>
#include <stdint.h>

// ---------------- problem constants ----------------
#define BATCH 2
#define GRID_DIM 32
#define C_DIM 192
#define HEADS 6
#define HD 32
#define NTOK 64
#define NWIN 1024
#define M_TOT (NWIN * NTOK)
#define HID 768
#define SHIFT_AMT 2

// ---------------- scratch (device globals; no allocs) ----------------
__device__ __nv_bfloat16 g_xw[M_TOT * C_DIM];
__device__ __nv_bfloat16 g_qkv[3 * NWIN * HEADS * NTOK * HD]; // q pre-scaled
__device__ __nv_bfloat16 g_attnout[M_TOT * C_DIM];
__device__ float         g_xo[M_TOT * C_DIM];
__device__ __nv_bfloat16 g_xn2[M_TOT * C_DIM];
__device__ __nv_bfloat16 g_h1[M_TOT * HID];
// transposed bf16 weights [N][K]
__device__ __nv_bfloat16 g_wqkvT[576 * 192];
__device__ __nv_bfloat16 g_woT[192 * 192];
__device__ __nv_bfloat16 g_w1T[768 * 192];
__device__ __nv_bfloat16 g_w2T[192 * 768];

// ---------------- helpers ----------------
__device__ __forceinline__ float gelu_exact(float v) {
    return 0.5f * v * (1.0f + erff(v * 0.70710678118654752f));
}
__device__ __forceinline__ void mma_bf16(float (&c)[4], const uint32_t (&a)[4],
                                         const uint32_t b0, const uint32_t b1) {
    asm volatile(
        "mma.sync.aligned.m16n8k16.row.col.f32.bf16.bf16.f32 "
        "{%0,%1,%2,%3}, {%4,%5,%6,%7}, {%8,%9}, {%0,%1,%2,%3};"
        : "+f"(c[0]), "+f"(c[1]), "+f"(c[2]), "+f"(c[3])
        : "r"(a[0]), "r"(a[1]), "r"(a[2]), "r"(a[3]), "r"(b0), "r"(b1));
}
__device__ __forceinline__ void mma_bf16v(float (&c)[4], const uint32_t (&a)[4],
                                          const uint32_t (&b)[2]) {
    mma_bf16(c, a, b[0], b[1]);
}
__device__ __forceinline__ void ldm_x4(uint32_t (&r)[4], uint32_t addr) {
    asm volatile("ldmatrix.sync.aligned.m8n8.x4.shared.b16 {%0,%1,%2,%3}, [%4];"
                 : "=r"(r[0]), "=r"(r[1]), "=r"(r[2]), "=r"(r[3]) : "r"(addr));
}
__device__ __forceinline__ uint32_t packbf2(float a, float b) {
    __nv_bfloat162 t = __floats2bfloat162_rn(a, b);
    return *(uint32_t*)&t;
}
__device__ __forceinline__ uint32_t smem_u32(const void* p) {
    return (uint32_t)__cvta_generic_to_shared(p);
}
#define CP16(dst, src) \
    asm volatile("cp.async.cg.shared.global [%0], [%1], 16;" :: "r"(dst), "l"(src))
#define CP_COMMIT() asm volatile("cp.async.commit_group;")
#define CP_WAIT2()  asm volatile("cp.async.wait_group 2;")

__device__ __forceinline__ int winrow_to_orig(int t) {
    int wi = t >> 6, n = t & 63;
    int b  = wi >> 9;
    int Hb = (wi >> 6) & 7, Wb = (wi >> 3) & 7, Db = wi & 7;
    int i = n >> 4, j = (n >> 2) & 3, k = n & 3;
    int h = ((Hb << 2) + i + SHIFT_AMT) & 31;
    int w = ((Wb << 2) + j + SHIFT_AMT) & 31;
    int d = ((Db << 2) + k + SHIFT_AMT) & 31;
    return (((b * 32 + h) * 32 + w) * 32 + d);
}

// ---------------- weight prep: all four fp32 [K][N] -> bf16 [N][K] --------
#define W0 (576 * 192)
#define W1 (192 * 192)
#define W2 (768 * 192)
#define W3 (192 * 768)
__global__ __launch_bounds__(256) void prep_all(const float* __restrict__ wqkv,
                                                const float* __restrict__ wo,
                                                const float* __restrict__ w1,
                                                const float* __restrict__ w2) {
    int i = blockIdx.x * 256 + threadIdx.x;
    const float* src;
    __nv_bfloat16* dst;
    int K, N;
    if (i < W0)                       { src = wqkv; dst = g_wqkvT; K = 192; N = 576; }
    else if ((i -= W0) < W1)          { src = wo;   dst = g_woT;   K = 192; N = 192; }
    else if ((i -= W1) < W2)          { src = w1;   dst = g_w1T;   K = 192; N = 768; }
    else if ((i -= W2) < W3)          { src = w2;   dst = g_w2T;   K = 768; N = 192; }
    else return;
    int n = i / K, k = i - n * K;
    dst[i] = __float2bfloat16(src[k * N + n]);
}

// ---------------- LN kernels (warp per token), bf16 output ----------------
__global__ __launch_bounds__(256) void ln_kernel(const float* __restrict__ xin,
                                                 const float* __restrict__ gma,
                                                 const float* __restrict__ bta,
                                                 int mode) {
    int warp = threadIdx.x >> 5, lane = threadIdx.x & 31;
    int t = blockIdx.x * 8 + warp;
    const float* src;
    __nv_bfloat16* dst;
    if (mode == 0) {
        src = xin + (size_t)winrow_to_orig(t) * C_DIM;
        dst = g_xw + (size_t)t * C_DIM;
    } else {
        src = g_xo + (size_t)t * C_DIM;
        dst = g_xn2 + (size_t)t * C_DIM;
    }
    float v[6];
    float s = 0.f;
#pragma unroll
    for (int k = 0; k < 6; k++) { v[k] = src[lane + 32 * k]; s += v[k]; }
#pragma unroll
    for (int o = 16; o > 0; o >>= 1) s += __shfl_xor_sync(0xffffffffu, s, o);
    float mean = s * (1.0f / C_DIM);
    float q = 0.f;
#pragma unroll
    for (int k = 0; k < 6; k++) { float d = v[k] - mean; q += d * d; }
#pragma unroll
    for (int o = 16; o > 0; o >>= 1) q += __shfl_xor_sync(0xffffffffu, q, o);
    float rstd = rsqrtf(q * (1.0f / C_DIM) + 1e-5f);
#pragma unroll
    for (int k = 0; k < 6; k++) {
        int c = lane + 32 * k;
        dst[c] = __float2bfloat16((v[k] - mean) * rstd * gma[c] + bta[c]);
    }
}

// ---------------- bf16 GEMM: ldmatrix + 4-stage cp.async ----------------
// Block tile 128x64, k-step 32, 256 threads = 8 warps (4x2), warp tile 32x32.
__global__ __launch_bounds__(256) void gemm_bf16(const __nv_bfloat16* __restrict__ BwT,
                                                 const float* __restrict__ bias,
                                                 const float* __restrict__ xres,
                                                 float* __restrict__ dout,
                                                 int K, int N, int mode) {
    const __nv_bfloat16* A = (mode == 0) ? g_xw
                           : (mode == 1) ? g_attnout
                           : (mode == 2) ? g_xn2
                                         : g_h1;
    __shared__ __nv_bfloat16 AsH[4][128 * 40];   // [m][k], stride 40
    __shared__ __nv_bfloat16 BsH[4][64 * 40];    // [n][k], stride 40

    int tid = threadIdx.x;
    int warp = tid >> 5, lane = tid & 31;
    int gid = lane >> 2, tig = lane & 3;
    int warpM = warp & 3, warpN = warp >> 2;
    int row0 = blockIdx.y * 128, col0 = blockIdx.x * 64;

    // cp.async coordinates
    int aRow = tid >> 1, aCol = (tid & 1) * 16;
    int bRow = tid >> 2, bCol = (tid & 3) * 8;
    const __nv_bfloat16* aSrc = A + (size_t)(row0 + aRow) * K + aCol;
    const __nv_bfloat16* bSrc = BwT + (size_t)(col0 + bRow) * K + bCol;

    // ldmatrix element offsets (within a stage)
    // A: per mt, lanes 0-15 -> rows m0+(lane&15), k+0; lanes 16-31 -> same rows, k+8
    int aLdmRow[2], bLdmRow;
    int aKoff = (lane >> 4) << 3;
#pragma unroll
    for (int mt = 0; mt < 2; mt++)
        aLdmRow[mt] = (warpM * 32 + mt * 16 + (lane & 15)) * 40 + aKoff;
    // B: per nt-pair p, lane groups of 8: {nt=2p rows,k0},{nt=2p,k8},{nt=2p+1,k0},{nt=2p+1,k8}
    int bKoff = ((lane >> 3) & 1) << 3;
    bLdmRow = (warpN * 32 + ((lane >> 4) << 3) + (lane & 7)) * 40 + bKoff;

    int NK = K >> 5;

    float acc[2][4][4];
#pragma unroll
    for (int mt = 0; mt < 2; mt++)
#pragma unroll
        for (int nt = 0; nt < 4; nt++)
#pragma unroll
            for (int i = 0; i < 4; i++) acc[mt][nt][i] = 0.f;

    // prologue: stages 0,1,2
#pragma unroll
    for (int s = 0; s < 3; s++) {
        if (s < NK) {
            uint32_t ad = smem_u32(&AsH[s][aRow * 40 + aCol]);
            CP16(ad, aSrc + s * 32);
            CP16(ad + 16, aSrc + s * 32 + 8);
            uint32_t bd = smem_u32(&BsH[s][bRow * 40 + bCol]);
            CP16(bd, bSrc + s * 32);
        }
        CP_COMMIT();
    }

    for (int ki = 0; ki < NK; ki++) {
        CP_WAIT2();
        __syncthreads();
        int kn = ki + 3;
        if (kn < NK) {
            int st = kn & 3;
            uint32_t ad = smem_u32(&AsH[st][aRow * 40 + aCol]);
            CP16(ad, aSrc + kn * 32);
            CP16(ad + 16, aSrc + kn * 32 + 8);
            uint32_t bd = smem_u32(&BsH[st][bRow * 40 + bCol]);
            CP16(bd, bSrc + kn * 32);
        }
        CP_COMMIT();

        int s = ki & 3;
        uint32_t aBase = smem_u32(&AsH[s][0]);
        uint32_t bBase = smem_u32(&BsH[s][0]);
#pragma unroll
        for (int kk = 0; kk < 32; kk += 16) {
            uint32_t afr[2][4];
#pragma unroll
            for (int mt = 0; mt < 2; mt++)
                ldm_x4(afr[mt], aBase + (aLdmRow[mt] + kk) * 2);
#pragma unroll
            for (int p = 0; p < 2; p++) {
                uint32_t bfr[4];
                ldm_x4(bfr, bBase + (bLdmRow + p * 16 * 40 + kk) * 2);
#pragma unroll
                for (int mt = 0; mt < 2; mt++) {
                    mma_bf16(acc[mt][2 * p + 0], afr[mt], bfr[0], bfr[1]);
                    mma_bf16(acc[mt][2 * p + 1], afr[mt], bfr[2], bfr[3]);
                }
            }
        }
    }

    const float QK_SCALE = 0.17677669529663687f;
#pragma unroll
    for (int mt = 0; mt < 2; mt++) {
        int rbase = row0 + warpM * 32 + mt * 16 + gid;
#pragma unroll
        for (int half = 0; half < 2; half++) {
            int row = rbase + half * 8;
            int obase1 = 0;
            if (mode == 1) obase1 = winrow_to_orig(row) * C_DIM;
#pragma unroll
            for (int nt = 0; nt < 4; nt++) {
                int col = col0 + warpN * 32 + nt * 8 + 2 * tig;
                float v0 = acc[mt][nt][half * 2 + 0] + bias[col];
                float v1 = acc[mt][nt][half * 2 + 1] + bias[col + 1];
                if (mode == 0) {
                    int wi = row >> 6, n = row & 63;
                    int which = col / 192;
                    int rem = col - which * 192;
                    int head = rem >> 5, hdi = rem & 31;
                    float sc = (which == 0) ? QK_SCALE : 1.0f;
                    uint32_t* p = (uint32_t*)&g_qkv[(((which * NWIN + wi) * HEADS + head) << 11) + (n << 5) + hdi];
                    *p = packbf2(v0 * sc, v1 * sc);
                } else if (mode == 1) {
                    float* p = &g_xo[obase1 + col];
                    const float* r = &xres[obase1 + col];
                    *(float2*)p = make_float2(v0 + r[0], v1 + r[1]);
                } else if (mode == 2) {
                    uint32_t* p = (uint32_t*)&g_h1[(size_t)row * HID + col];
                    *p = packbf2(gelu_exact(v0), gelu_exact(v1));
                } else {
                    size_t o = (size_t)row * C_DIM + col;
                    *(float2*)&dout[o] = make_float2(v0 + g_xo[o], v1 + g_xo[o + 1]);
                }
            }
        }
    }
}

// ---------------- attention: tensor-core, 1 block per (window, head) -------
__global__ __launch_bounds__(128) void attn_kernel(const float* __restrict__ bias_table) {
    __shared__ __nv_bfloat16 sQ[64 * 40];
    __shared__ __nv_bfloat16 sK[64 * 40];
    __shared__ __nv_bfloat16 sVT[32 * 72];
    __shared__ float sBias[343];
    __shared__ unsigned char sReg[64];

    int wi = blockIdx.x / HEADS, head = blockIdx.x % HEADS;
    int tid = threadIdx.x;
    int warp = tid >> 5, lane = tid & 31;
    int g = lane >> 2, q4 = lane & 3;

    const __nv_bfloat16* Qg = g_qkv + (((0 * NWIN + wi) * HEADS + head) << 11);
    const __nv_bfloat16* Kg = g_qkv + (((1 * NWIN + wi) * HEADS + head) << 11);
    const __nv_bfloat16* Vg = g_qkv + (((2 * NWIN + wi) * HEADS + head) << 11);

#pragma unroll
    for (int i = tid; i < 256; i += 128) {
        int r = i >> 2, c = (i & 3) * 8;
        *(uint4*)&sQ[r * 40 + c] = *(const uint4*)&Qg[r * 32 + c];
        *(uint4*)&sK[r * 40 + c] = *(const uint4*)&Kg[r * 32 + c];
        uint4 v = *(const uint4*)&Vg[r * 32 + c];
        __nv_bfloat16 tmp[8];
        *(uint4*)tmp = v;
#pragma unroll
        for (int j = 0; j < 8; j++) sVT[(c + j) * 72 + r] = tmp[j];
    }
    if (tid < 64) {
        int Hb = (wi >> 6) & 7, Wb = (wi >> 3) & 7, Db = wi & 7;
        int ih = tid >> 4, iw = (tid >> 2) & 3, id = tid & 3;
        int rh = (Hb == 7) ? (ih >= 2 ? 2 : 1) : 0;
        int rw = (Wb == 7) ? (iw >= 2 ? 2 : 1) : 0;
        int rd = (Db == 7) ? (id >= 2 ? 2 : 1) : 0;
        sReg[tid] = (unsigned char)(rh * 9 + rw * 3 + rd);
    }
    for (int i = tid; i < 343; i += 128) sBias[i] = bias_table[i * HEADS + head];
    __syncthreads();

    int m0 = warp * 16;
    uint32_t af[2][4];
#pragma unroll
    for (int kt = 0; kt < 2; kt++) {
        int kk = kt * 16;
        af[kt][0] = *(const uint32_t*)&sQ[(m0 + g) * 40 + kk + 2 * q4];
        af[kt][1] = *(const uint32_t*)&sQ[(m0 + g + 8) * 40 + kk + 2 * q4];
        af[kt][2] = *(const uint32_t*)&sQ[(m0 + g) * 40 + kk + 8 + 2 * q4];
        af[kt][3] = *(const uint32_t*)&sQ[(m0 + g + 8) * 40 + kk + 8 + 2 * q4];
    }
    float c[8][4];
#pragma unroll
    for (int nt = 0; nt < 8; nt++)
#pragma unroll
        for (int i = 0; i < 4; i++) c[nt][i] = 0.f;
#pragma unroll
    for (int nt = 0; nt < 8; nt++) {
#pragma unroll
        for (int kt = 0; kt < 2; kt++) {
            uint32_t bf[2];
            bf[0] = *(const uint32_t*)&sK[(nt * 8 + g) * 40 + kt * 16 + 2 * q4];
            bf[1] = *(const uint32_t*)&sK[(nt * 8 + g) * 40 + kt * 16 + 8 + 2 * q4];
            mma_bf16v(c[nt], af[kt], bf);
        }
    }

    int i0 = m0 + g, i1 = i0 + 8;
    int base0 = (i0 >> 4) * 49 + ((i0 >> 2) & 3) * 7 + (i0 & 3);
    int base1 = (i1 >> 4) * 49 + ((i1 >> 2) & 3) * 7 + (i1 & 3);
    int r0 = sReg[i0], r1 = sReg[i1];
#pragma unroll
    for (int nt = 0; nt < 8; nt++) {
#pragma unroll
        for (int e = 0; e < 2; e++) {
            int j = nt * 8 + 2 * q4 + e;
            int jb = (j >> 4) * 49 + ((j >> 2) & 3) * 7 + (j & 3);
            int rj = sReg[j];
            c[nt][e]     += sBias[base0 - jb + 171] + ((r0 == rj) ? 0.f : -100.f);
            c[nt][2 + e] += sBias[base1 - jb + 171] + ((r1 == rj) ? 0.f : -100.f);
        }
    }

    float mx0 = -1e30f, mx1 = -1e30f;
#pragma unroll
    for (int nt = 0; nt < 8; nt++) {
        mx0 = fmaxf(mx0, fmaxf(c[nt][0], c[nt][1]));
        mx1 = fmaxf(mx1, fmaxf(c[nt][2], c[nt][3]));
    }
    mx0 = fmaxf(mx0, __shfl_xor_sync(0xffffffffu, mx0, 1));
    mx0 = fmaxf(mx0, __shfl_xor_sync(0xffffffffu, mx0, 2));
    mx1 = fmaxf(mx1, __shfl_xor_sync(0xffffffffu, mx1, 1));
    mx1 = fmaxf(mx1, __shfl_xor_sync(0xffffffffu, mx1, 2));
    float s0 = 0.f, s1 = 0.f;
#pragma unroll
    for (int nt = 0; nt < 8; nt++) {
        c[nt][0] = __expf(c[nt][0] - mx0); s0 += c[nt][0];
        c[nt][1] = __expf(c[nt][1] - mx0); s0 += c[nt][1];
        c[nt][2] = __expf(c[nt][2] - mx1); s1 += c[nt][2];
        c[nt][3] = __expf(c[nt][3] - mx1); s1 += c[nt][3];
    }
    s0 += __shfl_xor_sync(0xffffffffu, s0, 1);
    s0 += __shfl_xor_sync(0xffffffffu, s0, 2);
    s1 += __shfl_xor_sync(0xffffffffu, s1, 1);
    s1 += __shfl_xor_sync(0xffffffffu, s1, 2);
    float inv0 = 1.0f / s0, inv1 = 1.0f / s1;
#pragma unroll
    for (int nt = 0; nt < 8; nt++) {
        c[nt][0] *= inv0; c[nt][1] *= inv0;
        c[nt][2] *= inv1; c[nt][3] *= inv1;
    }

    uint32_t pa[4][4];
#pragma unroll
    for (int kt = 0; kt < 4; kt++) {
        pa[kt][0] = packbf2(c[2 * kt][0], c[2 * kt][1]);
        pa[kt][1] = packbf2(c[2 * kt][2], c[2 * kt][3]);
        pa[kt][2] = packbf2(c[2 * kt + 1][0], c[2 * kt + 1][1]);
        pa[kt][3] = packbf2(c[2 * kt + 1][2], c[2 * kt + 1][3]);
    }
    float d[4][4];
#pragma unroll
    for (int nt = 0; nt < 4; nt++)
#pragma unroll
        for (int i = 0; i < 4; i++) d[nt][i] = 0.f;
#pragma unroll
    for (int nt = 0; nt < 4; nt++) {
#pragma unroll
        for (int kt = 0; kt < 4; kt++) {
            uint32_t bf[2];
            bf[0] = *(const uint32_t*)&sVT[(nt * 8 + g) * 72 + kt * 16 + 2 * q4];
            bf[1] = *(const uint32_t*)&sVT[(nt * 8 + g) * 72 + kt * 16 + 8 + 2 * q4];
            mma_bf16v(d[nt], pa[kt], bf);
        }
    }

    size_t ob0 = (size_t)(wi * 64 + i0) * C_DIM + head * 32;
    size_t ob1 = (size_t)(wi * 64 + i1) * C_DIM + head * 32;
#pragma unroll
    for (int nt = 0; nt < 4; nt++) {
        int col = nt * 8 + 2 * q4;
        *(uint32_t*)&g_attnout[ob0 + col] = packbf2(d[nt][0], d[nt][1]);
        *(uint32_t*)&g_attnout[ob1 + col] = packbf2(d[nt][2], d[nt][3]);
    }
}

extern "C" void kernel_launch(void* const* d_in, const int* in_sizes, int n_in,
                              void* d_out, int out_size) {
    const float* x          = (const float*)d_in[0];
    const float* g1         = (const float*)d_in[1];
    const float* b1         = (const float*)d_in[2];
    const float* wqkv       = (const float*)d_in[3];
    const float* bqkv       = (const float*)d_in[4];
    const float* wo         = (const float*)d_in[5];
    const float* bo         = (const float*)d_in[6];
    const float* bias_table = (const float*)d_in[7];
    const float* g2         = (const float*)d_in[8];
    const float* b2         = (const float*)d_in[9];
    const float* w1         = (const float*)d_in[10];
    const float* bm1        = (const float*)d_in[11];
    const float* w2         = (const float*)d_in[12];
    const float* bm2        = (const float*)d_in[13];
    float* out              = (float*)d_out;

    __nv_bfloat16 *wqkvT, *woT, *w1T, *w2T;
    cudaGetSymbolAddress((void**)&wqkvT, g_wqkvT);
    cudaGetSymbolAddress((void**)&woT, g_woT);
    cudaGetSymbolAddress((void**)&w1T, g_w1T);
    cudaGetSymbolAddress((void**)&w2T, g_w2T);

    // 0. weight prep (one launch)
    prep_all<<<(W0 + W1 + W2 + W3 + 255) / 256, 256>>>(wqkv, wo, w1, w2);
    // 1. LN1 + shift + window partition
    ln_kernel<<<M_TOT / 8, 256>>>(x, g1, b1, 0);
    // 2. QKV projection
    gemm_bf16<<<dim3(576 / 64, M_TOT / 128), 256>>>(wqkvT, bqkv, nullptr, nullptr, C_DIM, 576, 0);
    // 3. windowed attention
    attn_kernel<<<NWIN * HEADS, 128>>>(bias_table);
    // 4. output projection + reverse shift + residual
    gemm_bf16<<<dim3(192 / 64, M_TOT / 128), 256>>>(woT, bo, x, nullptr, C_DIM, C_DIM, 1);
    // 5. LN2
    ln_kernel<<<M_TOT / 8, 256>>>(nullptr, g2, b2, 1);
    // 6. fc1 + gelu
    gemm_bf16<<<dim3(768 / 64, M_TOT / 128), 256>>>(w1T, bm1, nullptr, nullptr, C_DIM, HID, 2);
    // 7. fc2 + residual -> out
    gemm_bf16<<<dim3(192 / 64, M_TOT / 128), 256>>>(w2T, bm2, nullptr, out, HID, C_DIM, 3);
}